// round 2
// baseline (speedup 1.0000x reference)
#include <cuda_runtime.h>
#include <cuda_bf16.h>

// Problem constants
constexpr int B_   = 4;
constexpr int T_   = 2048;
constexpr int C_   = 1024;
constexpr int H_   = 16;
constexpr int DH_  = 64;
constexpr int M_   = B_ * T_;          // 8192 rows
constexpr int N_QKV = 3 * C_;          // 3072

// Scratch (no cudaMalloc allowed)
__device__ float g_qkv[(size_t)M_ * N_QKV];   // [8192, 3072]  Q|K|V
__device__ float g_att[(size_t)M_ * C_];      // [8192, 1024]  attention output

// ---------------------------------------------------------------------------
// NT GEMM: C[m,n] = sum_k A[m,k] * B[n,k]   (A row-major [M,K], B row-major [N,K])
// 64x64 tile, BK=16, 256 threads, 4x4 per-thread outer product.
// ---------------------------------------------------------------------------
__global__ __launch_bounds__(256)
void gemm_nt_kernel(const float* __restrict__ A,
                    const float* __restrict__ Bm,
                    float* __restrict__ Cm,
                    int M, int N, int K)
{
    __shared__ float As[64 * 17];
    __shared__ float Bs[64 * 17];

    const int t  = threadIdx.x;
    const int ty = t >> 4;          // 0..15
    const int tx = t & 15;          // 0..15
    const int m0 = blockIdx.y * 64;
    const int n0 = blockIdx.x * 64;

    const int lr = t >> 2;          // 0..63 row for loads
    const int ls = (t & 3) * 4;     // 0,4,8,12 k-offset (float4)

    float acc[4][4];
#pragma unroll
    for (int i = 0; i < 4; i++)
#pragma unroll
        for (int j = 0; j < 4; j++) acc[i][j] = 0.f;

    for (int k0 = 0; k0 < K; k0 += 16) {
        float4 av = *reinterpret_cast<const float4*>(&A[(size_t)(m0 + lr) * K + k0 + ls]);
        float4 bv = *reinterpret_cast<const float4*>(&Bm[(size_t)(n0 + lr) * K + k0 + ls]);
        As[lr * 17 + ls + 0] = av.x;
        As[lr * 17 + ls + 1] = av.y;
        As[lr * 17 + ls + 2] = av.z;
        As[lr * 17 + ls + 3] = av.w;
        Bs[lr * 17 + ls + 0] = bv.x;
        Bs[lr * 17 + ls + 1] = bv.y;
        Bs[lr * 17 + ls + 2] = bv.z;
        Bs[lr * 17 + ls + 3] = bv.w;
        __syncthreads();

#pragma unroll
        for (int k = 0; k < 16; k++) {
            float a[4], b[4];
#pragma unroll
            for (int i = 0; i < 4; i++) a[i] = As[(ty * 4 + i) * 17 + k];
#pragma unroll
            for (int j = 0; j < 4; j++) b[j] = Bs[(tx * 4 + j) * 17 + k];
#pragma unroll
            for (int i = 0; i < 4; i++)
#pragma unroll
                for (int j = 0; j < 4; j++) acc[i][j] += a[i] * b[j];
        }
        __syncthreads();
    }

#pragma unroll
    for (int i = 0; i < 4; i++) {
        float4 o;
        o.x = acc[i][0]; o.y = acc[i][1]; o.z = acc[i][2]; o.w = acc[i][3];
        *reinterpret_cast<float4*>(&Cm[(size_t)(m0 + ty * 4 + i) * N + n0 + tx * 4]) = o;
    }
}

// ---------------------------------------------------------------------------
// Flash-style causal attention.
// One CTA per (q-tile of 64, b*H + h). 256 threads.
// Dynamic smem: Qs[64*64] + Ks[64*65] + Vs[64*65] + Ss[64*65] = 66304 bytes.
// ---------------------------------------------------------------------------
constexpr int ATTN_SMEM = (64 * 64 + 3 * 64 * 65) * 4;

__global__ __launch_bounds__(256)
void attn_kernel(const float* __restrict__ qkv, float* __restrict__ out)
{
    extern __shared__ float sm[];
    float* Qs = sm;                     // [64][64]
    float* Ks = sm + 64 * 64;           // [64][65]
    float* Vs = Ks + 64 * 65;           // [64][65]
    float* Ss = Vs + 64 * 65;           // [64][65]

    __shared__ float m_s[64], l_s[64], sc_s[64], red[256];

    const int t  = threadIdx.x;
    const int ty = t >> 4;
    const int tx = t & 15;
    const int bh = blockIdx.y;
    const int b  = bh >> 4;
    const int h  = bh & 15;
    const int qt = blockIdx.x;
    const int q0 = qt * 64;

    // Full 64x64 tile loads: row = (t>>4) + 16*rr (rr=0..3), col = (t&15)*4
    const int lrow = t >> 4;            // 0..15
    const int lcol = (t & 15) * 4;      // 0..60

    const float scale = 0.125f;         // 1/sqrt(64)

    // Load (pre-scaled) Q tile — 4 slabs of 16 rows
#pragma unroll
    for (int rr = 0; rr < 4; rr++) {
        const int row = lrow + rr * 16;
        const float* qb = qkv + (size_t)(b * T_ + q0 + row) * N_QKV + h * DH_ + lcol;
        float4 v = *reinterpret_cast<const float4*>(qb);
        Qs[row * 64 + lcol + 0] = v.x * scale;
        Qs[row * 64 + lcol + 1] = v.y * scale;
        Qs[row * 64 + lcol + 2] = v.z * scale;
        Qs[row * 64 + lcol + 3] = v.w * scale;
    }
    if (t < 64) { m_s[t] = -1e30f; l_s[t] = 0.f; }

    float acc[4][4];
#pragma unroll
    for (int i = 0; i < 4; i++)
#pragma unroll
        for (int j = 0; j < 4; j++) acc[i][j] = 0.f;

    __syncthreads();

    for (int kt = 0; kt <= qt; kt++) {
        const int k0 = kt * 64;
        // Load K,V tiles — full 64x64 each
#pragma unroll
        for (int rr = 0; rr < 4; rr++) {
            const int row = lrow + rr * 16;
            const float* kb = qkv + (size_t)(b * T_ + k0 + row) * N_QKV + C_ + h * DH_ + lcol;
            float4 kv = *reinterpret_cast<const float4*>(kb);
            float4 vv = *reinterpret_cast<const float4*>(kb + C_);
            Ks[row * 65 + lcol + 0] = kv.x;
            Ks[row * 65 + lcol + 1] = kv.y;
            Ks[row * 65 + lcol + 2] = kv.z;
            Ks[row * 65 + lcol + 3] = kv.w;
            Vs[row * 65 + lcol + 0] = vv.x;
            Vs[row * 65 + lcol + 1] = vv.y;
            Vs[row * 65 + lcol + 2] = vv.z;
            Vs[row * 65 + lcol + 3] = vv.w;
        }
        __syncthreads();

        // S = Q * K^T  (already scaled)
        float s[4][4];
#pragma unroll
        for (int i = 0; i < 4; i++)
#pragma unroll
            for (int j = 0; j < 4; j++) s[i][j] = 0.f;
#pragma unroll
        for (int d = 0; d < 64; d++) {
            float a[4], bb[4];
#pragma unroll
            for (int i = 0; i < 4; i++) a[i]  = Qs[(ty * 4 + i) * 64 + d];
#pragma unroll
            for (int j = 0; j < 4; j++) bb[j] = Ks[(tx * 4 + j) * 65 + d];
#pragma unroll
            for (int i = 0; i < 4; i++)
#pragma unroll
                for (int j = 0; j < 4; j++) s[i][j] += a[i] * bb[j];
        }
        // causal mask (only diagonal tile needs it)
        if (kt == qt) {
#pragma unroll
            for (int i = 0; i < 4; i++)
#pragma unroll
                for (int j = 0; j < 4; j++)
                    if (k0 + tx * 4 + j > q0 + ty * 4 + i) s[i][j] = -1e30f;
        }
#pragma unroll
        for (int i = 0; i < 4; i++)
#pragma unroll
            for (int j = 0; j < 4; j++)
                Ss[(ty * 4 + i) * 65 + tx * 4 + j] = s[i][j];
        __syncthreads();

        // Online softmax update: each row handled by 4 threads (16 cols each)
        const int r  = t >> 2;
        const int c0 = (t & 3) * 16;
        float pm = -1e30f;
#pragma unroll
        for (int c = 0; c < 16; c++) pm = fmaxf(pm, Ss[r * 65 + c0 + c]);
        red[r * 4 + (t & 3)] = pm;
        __syncthreads();

        if (t < 64) {
            float mold = m_s[t];
            float mnew = fmaxf(fmaxf(red[t * 4], red[t * 4 + 1]),
                               fmaxf(red[t * 4 + 2], red[t * 4 + 3]));
            mnew = fmaxf(mnew, mold);
            m_s[t]  = mnew;
            sc_s[t] = __expf(mold - mnew);
        }
        __syncthreads();

        {
            float mnew = m_s[r];
            float ps = 0.f;
#pragma unroll
            for (int c = 0; c < 16; c++) {
                float e = __expf(Ss[r * 65 + c0 + c] - mnew);
                Ss[r * 65 + c0 + c] = e;
                ps += e;
            }
            red[r * 4 + (t & 3)] = ps;
        }
        __syncthreads();

        if (t < 64)
            l_s[t] = l_s[t] * sc_s[t] +
                     red[t * 4] + red[t * 4 + 1] + red[t * 4 + 2] + red[t * 4 + 3];

        // Rescale accumulators
#pragma unroll
        for (int i = 0; i < 4; i++) {
            float sc = sc_s[ty * 4 + i];
#pragma unroll
            for (int j = 0; j < 4; j++) acc[i][j] *= sc;
        }

        // O += P * V
#pragma unroll
        for (int kk = 0; kk < 64; kk++) {
            float p[4], v[4];
#pragma unroll
            for (int i = 0; i < 4; i++) p[i] = Ss[(ty * 4 + i) * 65 + kk];
#pragma unroll
            for (int j = 0; j < 4; j++) v[j] = Vs[kk * 65 + tx * 4 + j];
#pragma unroll
            for (int i = 0; i < 4; i++)
#pragma unroll
                for (int j = 0; j < 4; j++) acc[i][j] += p[i] * v[j];
        }
        __syncthreads();
    }

    // Normalize and store to [B*T, C] with head offset
#pragma unroll
    for (int i = 0; i < 4; i++) {
        float inv = 1.f / l_s[ty * 4 + i];
        float4 o;
        o.x = acc[i][0] * inv;
        o.y = acc[i][1] * inv;
        o.z = acc[i][2] * inv;
        o.w = acc[i][3] * inv;
        *reinterpret_cast<float4*>(
            &out[(size_t)(b * T_ + q0 + ty * 4 + i) * C_ + h * DH_ + tx * 4]) = o;
    }
}

// ---------------------------------------------------------------------------
extern "C" void kernel_launch(void* const* d_in, const int* in_sizes, int n_in,
                              void* d_out, int out_size)
{
    const float* x     = (const float*)d_in[0];   // [8192,1024]
    const float* w_qkv = (const float*)d_in[1];   // [3072,1024]
    const float* w_out = (const float*)d_in[2];   // [1024,1024]
    float*       out   = (float*)d_out;           // [8192,1024]

    float* qkv = nullptr;
    float* att = nullptr;
    cudaGetSymbolAddress((void**)&qkv, g_qkv);
    cudaGetSymbolAddress((void**)&att, g_att);

    cudaFuncSetAttribute(attn_kernel,
                         cudaFuncAttributeMaxDynamicSharedMemorySize, ATTN_SMEM);

    // 1) QKV projection: [8192,1024] x [3072,1024]^T -> [8192,3072]
    {
        dim3 grid(N_QKV / 64, M_ / 64);
        gemm_nt_kernel<<<grid, 256>>>(x, w_qkv, qkv, M_, N_QKV, C_);
    }
    // 2) Causal attention -> g_att [8192,1024]
    {
        dim3 grid(T_ / 64, B_ * H_);
        attn_kernel<<<grid, 256, ATTN_SMEM>>>(qkv, att);
    }
    // 3) Output projection: [8192,1024] x [1024,1024]^T -> out
    {
        dim3 grid(C_ / 64, M_ / 64);
        gemm_nt_kernel<<<grid, 256>>>(att, w_out, out, M_, C_, C_);
    }
}

// round 4
// speedup vs baseline: 1.7879x; 1.7879x over previous
#include <cuda_runtime.h>
#include <cuda_bf16.h>
#include <cstdint>

// ============================================================================
// Problem constants
// ============================================================================
constexpr int B_    = 4;
constexpr int T_    = 2048;
constexpr int C_    = 1024;
constexpr int H_    = 16;
constexpr int DH_   = 64;
constexpr int M_    = B_ * T_;        // 8192
constexpr int N_QKV = 3 * C_;         // 3072
constexpr int K3_   = 3 * C_;         // 3072 (hi|lo|hi concatenated K)

// ============================================================================
// Scratch (__device__ globals; no cudaMalloc allowed)
// ============================================================================
__device__ float          g_qkv[(size_t)M_ * N_QKV];      // [8192,3072] fp32
__device__ float          g_att[(size_t)M_ * C_];         // [8192,1024] fp32
__device__ __nv_bfloat16  g_x3[(size_t)M_ * K3_];         // [8192, 3072] hi|lo|hi
__device__ __nv_bfloat16  g_att3[(size_t)M_ * K3_];       // [8192, 3072] hi|lo|hi
__device__ __nv_bfloat16  g_wqkv3[(size_t)N_QKV * K3_];   // [3072, 3072] hi|hi|lo
__device__ __nv_bfloat16  g_wout3[(size_t)C_ * K3_];      // [1024, 3072] hi|hi|lo

// ============================================================================
// PTX helpers (base-ISA only: works on .target sm_103 without 'a' features)
// ============================================================================
__device__ __forceinline__ uint32_t smem_to_u32(const void* smem_ptr) {
    uint32_t addr;
    asm("{ .reg .u64 tmp; cvta.to.shared.u64 tmp, %1; cvt.u32.u64 %0, tmp; }"
        : "=r"(addr) : "l"(smem_ptr));
    return addr;
}

__device__ __forceinline__ void ldsm_x4(uint32_t (&r)[4], uint32_t addr) {
    asm volatile("ldmatrix.sync.aligned.m8n8.x4.shared.b16 {%0,%1,%2,%3}, [%4];"
        : "=r"(r[0]), "=r"(r[1]), "=r"(r[2]), "=r"(r[3]) : "r"(addr));
}
__device__ __forceinline__ void ldsm_x2(uint32_t (&r)[2], uint32_t addr) {
    asm volatile("ldmatrix.sync.aligned.m8n8.x2.shared.b16 {%0,%1}, [%2];"
        : "=r"(r[0]), "=r"(r[1]) : "r"(addr));
}
__device__ __forceinline__ void mma_bf16(float (&d)[4],
                                         const uint32_t (&a)[4],
                                         const uint32_t (&b)[2]) {
    asm volatile(
        "mma.sync.aligned.m16n8k16.row.col.f32.bf16.bf16.f32 "
        "{%0,%1,%2,%3}, {%4,%5,%6,%7}, {%8,%9}, {%0,%1,%2,%3};"
        : "+f"(d[0]), "+f"(d[1]), "+f"(d[2]), "+f"(d[3])
        : "r"(a[0]), "r"(a[1]), "r"(a[2]), "r"(a[3]), "r"(b[0]), "r"(b[1]));
}

#define CP_ASYNC_16(dst_u32, src_ptr) \
    asm volatile("cp.async.cg.shared.global [%0], [%1], 16;" \
        :: "r"(dst_u32), "l"(src_ptr))
#define CP_ASYNC_COMMIT() asm volatile("cp.async.commit_group;" ::: "memory")
#define CP_ASYNC_WAIT_1() asm volatile("cp.async.wait_group 1;" ::: "memory")
#define CP_ASYNC_WAIT_0() asm volatile("cp.async.wait_group 0;" ::: "memory")

__device__ __forceinline__ uint32_t sw128(uint32_t off) {
    return off ^ ((off >> 3) & 0x70);
}

// ============================================================================
// Split fp32 -> 3-slab bf16 along K:  out[row, slab*K + col]
//   slabs != lo_slab get hi = bf16(a); slab == lo_slab gets lo = bf16(a - hi)
//   A-type (activations): lo_slab = 1  -> [hi | lo | hi]
//   B-type (weights):     lo_slab = 2  -> [hi | hi | lo]
// ============================================================================
__global__ __launch_bounds__(256)
void split3_kernel(const float* __restrict__ in,
                   __nv_bfloat16* __restrict__ out3,
                   int K, int n4, int lo_slab)
{
    int i = blockIdx.x * blockDim.x + threadIdx.x;
    if (i >= n4) return;
    int e   = i * 4;
    int row = e / K;
    int col = e - row * K;
    float4 v = reinterpret_cast<const float4*>(in)[i];

    __nv_bfloat16 h0 = __float2bfloat16(v.x), h1 = __float2bfloat16(v.y);
    __nv_bfloat16 h2 = __float2bfloat16(v.z), h3 = __float2bfloat16(v.w);
    __nv_bfloat16 l0 = __float2bfloat16(v.x - __bfloat162float(h0));
    __nv_bfloat16 l1 = __float2bfloat16(v.y - __bfloat162float(h1));
    __nv_bfloat16 l2 = __float2bfloat16(v.z - __bfloat162float(h2));
    __nv_bfloat16 l3 = __float2bfloat16(v.w - __bfloat162float(h3));

    __nv_bfloat162 hA; hA.x = h0; hA.y = h1;
    __nv_bfloat162 hB; hB.x = h2; hB.y = h3;
    __nv_bfloat162 lA; lA.x = l0; lA.y = l1;
    __nv_bfloat162 lB; lB.x = l2; lB.y = l3;

    size_t base = (size_t)row * (3 * K) + col;
#pragma unroll
    for (int slab = 0; slab < 3; slab++) {
        __nv_bfloat162* p =
            reinterpret_cast<__nv_bfloat162*>(out3 + base + (size_t)slab * K);
        if (slab == lo_slab) { p[0] = lA; p[1] = lB; }
        else                 { p[0] = hA; p[1] = hB; }
    }
}

// ============================================================================
// bf16 NT GEMM via mma.sync (HMMA): C[m,n] = sum_k A[m,k] * B[n,k]
// Tile 128x128, BK=64, 256 threads (8 warps, each 64x32), cp.async 2-stage.
// ============================================================================
constexpr int BM = 128, BN = 128, BK = 64;
constexpr int TILEB     = BM * 128;        // 16384 B per A/B tile (128B rows)
constexpr int GEMM_SMEM = 4 * TILEB;       // 2 stages x (A + B) = 64 KB

__device__ __forceinline__ void gemm_issue_loads(
    const __nv_bfloat16* __restrict__ A, const __nv_bfloat16* __restrict__ Bm,
    int K, int m0, int n0, int kc, uint32_t abase, uint32_t bbase, int tid)
{
#pragma unroll
    for (int s = 0; s < 4; s++) {
        const int idx = tid + s * 256;     // 0..1023
        const int r = idx >> 3;            // row 0..127
        const int c = idx & 7;             // 16B chunk 0..7
        const uint32_t so = sw128((uint32_t)(r * 128 + c * 16));
        const __nv_bfloat16* ga = A  + (size_t)(m0 + r) * K + kc + c * 8;
        const __nv_bfloat16* gb = Bm + (size_t)(n0 + r) * K + kc + c * 8;
        CP_ASYNC_16(abase + so, ga);
        CP_ASYNC_16(bbase + so, gb);
    }
}

__global__ __launch_bounds__(256, 2)
void gemm_mma_kernel(const __nv_bfloat16* __restrict__ A,
                     const __nv_bfloat16* __restrict__ Bm,
                     float* __restrict__ Cm,
                     int M, int N, int K)
{
    extern __shared__ char sm[];
    const int tid  = threadIdx.x;
    const int wid  = tid >> 5;
    const int lane = tid & 31;
    const int m0 = blockIdx.y * BM;
    const int n0 = blockIdx.x * BN;
    const int wm = (wid & 1) * 64;     // warp M offset within tile
    const int wn = (wid >> 1) * 32;    // warp N offset within tile

    const uint32_t sbase = smem_to_u32(sm);
    // stage b: A at b*2*TILEB, B at b*2*TILEB + TILEB

    float acc[4][4][4];
#pragma unroll
    for (int mi = 0; mi < 4; mi++)
#pragma unroll
        for (int ni = 0; ni < 4; ni++)
#pragma unroll
            for (int e = 0; e < 4; e++) acc[mi][ni][e] = 0.f;

    const int NC = K / BK;

    gemm_issue_loads(A, Bm, K, m0, n0, 0, sbase, sbase + TILEB, tid);
    CP_ASYNC_COMMIT();

    for (int ch = 0; ch < NC; ch++) {
        if (ch + 1 < NC) {
            const uint32_t nb = ((ch + 1) & 1) ? (uint32_t)(2 * TILEB) : 0u;
            gemm_issue_loads(A, Bm, K, m0, n0, (ch + 1) * BK,
                             sbase + nb, sbase + nb + TILEB, tid);
            CP_ASYNC_COMMIT();
            CP_ASYNC_WAIT_1();
        } else {
            CP_ASYNC_WAIT_0();
        }
        __syncthreads();

        const uint32_t abase = sbase + ((ch & 1) ? (uint32_t)(2 * TILEB) : 0u);
        const uint32_t bbase = abase + TILEB;

#pragma unroll
        for (int ks = 0; ks < 4; ks++) {
            uint32_t afr[4][4];
#pragma unroll
            for (int mi = 0; mi < 4; mi++) {
                const int row = wm + mi * 16 + (lane & 15);
                const uint32_t off =
                    sw128((uint32_t)(row * 128 + ks * 32 + ((lane >> 4) & 1) * 16));
                ldsm_x4(afr[mi], abase + off);
            }
            uint32_t bfr[4][2];
#pragma unroll
            for (int ni = 0; ni < 4; ni++) {
                const int row = wn + ni * 8 + (lane & 7);
                const uint32_t off =
                    sw128((uint32_t)(row * 128 + ks * 32 + ((lane >> 3) & 1) * 16));
                ldsm_x2(bfr[ni], bbase + off);
            }
#pragma unroll
            for (int mi = 0; mi < 4; mi++)
#pragma unroll
                for (int ni = 0; ni < 4; ni++)
                    mma_bf16(acc[mi][ni], afr[mi], bfr[ni]);
        }
        __syncthreads();
    }

    // Epilogue: direct fp32 stores (float2 per 8x8 quadrant row)
    const int g  = lane >> 2;          // 0..7
    const int tg = lane & 3;           // 0..3
#pragma unroll
    for (int mi = 0; mi < 4; mi++) {
#pragma unroll
        for (int ni = 0; ni < 4; ni++) {
            const int row = m0 + wm + mi * 16 + g;
            const int col = n0 + wn + ni * 8 + tg * 2;
            float2 p0; p0.x = acc[mi][ni][0]; p0.y = acc[mi][ni][1];
            float2 p1; p1.x = acc[mi][ni][2]; p1.y = acc[mi][ni][3];
            *reinterpret_cast<float2*>(&Cm[(size_t)row * N + col])       = p0;
            *reinterpret_cast<float2*>(&Cm[(size_t)(row + 8) * N + col]) = p1;
        }
    }
}

// ============================================================================
// Flash-style causal attention (unchanged from passing R2 version).
// ============================================================================
constexpr int ATTN_SMEM = (64 * 64 + 3 * 64 * 65) * 4;

__global__ __launch_bounds__(256)
void attn_kernel(const float* __restrict__ qkv, float* __restrict__ out)
{
    extern __shared__ float smf[];
    float* Qs = smf;
    float* Ks = smf + 64 * 64;
    float* Vs = Ks + 64 * 65;
    float* Ss = Vs + 64 * 65;

    __shared__ float m_s[64], l_s[64], sc_s[64], red[256];

    const int t  = threadIdx.x;
    const int ty = t >> 4;
    const int tx = t & 15;
    const int bh = blockIdx.y;
    const int b  = bh >> 4;
    const int h  = bh & 15;
    const int qt = blockIdx.x;
    const int q0 = qt * 64;

    const int lrow = t >> 4;
    const int lcol = (t & 15) * 4;

    const float scale = 0.125f;

#pragma unroll
    for (int rr = 0; rr < 4; rr++) {
        const int row = lrow + rr * 16;
        const float* qb = qkv + (size_t)(b * T_ + q0 + row) * N_QKV + h * DH_ + lcol;
        float4 v = *reinterpret_cast<const float4*>(qb);
        Qs[row * 64 + lcol + 0] = v.x * scale;
        Qs[row * 64 + lcol + 1] = v.y * scale;
        Qs[row * 64 + lcol + 2] = v.z * scale;
        Qs[row * 64 + lcol + 3] = v.w * scale;
    }
    if (t < 64) { m_s[t] = -1e30f; l_s[t] = 0.f; }

    float acc[4][4];
#pragma unroll
    for (int i = 0; i < 4; i++)
#pragma unroll
        for (int j = 0; j < 4; j++) acc[i][j] = 0.f;

    __syncthreads();

    for (int kt = 0; kt <= qt; kt++) {
        const int k0 = kt * 64;
#pragma unroll
        for (int rr = 0; rr < 4; rr++) {
            const int row = lrow + rr * 16;
            const float* kb = qkv + (size_t)(b * T_ + k0 + row) * N_QKV + C_ + h * DH_ + lcol;
            float4 kv = *reinterpret_cast<const float4*>(kb);
            float4 vv = *reinterpret_cast<const float4*>(kb + C_);
            Ks[row * 65 + lcol + 0] = kv.x;
            Ks[row * 65 + lcol + 1] = kv.y;
            Ks[row * 65 + lcol + 2] = kv.z;
            Ks[row * 65 + lcol + 3] = kv.w;
            Vs[row * 65 + lcol + 0] = vv.x;
            Vs[row * 65 + lcol + 1] = vv.y;
            Vs[row * 65 + lcol + 2] = vv.z;
            Vs[row * 65 + lcol + 3] = vv.w;
        }
        __syncthreads();

        float s[4][4];
#pragma unroll
        for (int i = 0; i < 4; i++)
#pragma unroll
            for (int j = 0; j < 4; j++) s[i][j] = 0.f;
#pragma unroll
        for (int d = 0; d < 64; d++) {
            float a[4], bb[4];
#pragma unroll
            for (int i = 0; i < 4; i++) a[i]  = Qs[(ty * 4 + i) * 64 + d];
#pragma unroll
            for (int j = 0; j < 4; j++) bb[j] = Ks[(tx * 4 + j) * 65 + d];
#pragma unroll
            for (int i = 0; i < 4; i++)
#pragma unroll
                for (int j = 0; j < 4; j++) s[i][j] += a[i] * bb[j];
        }
        if (kt == qt) {
#pragma unroll
            for (int i = 0; i < 4; i++)
#pragma unroll
                for (int j = 0; j < 4; j++)
                    if (k0 + tx * 4 + j > q0 + ty * 4 + i) s[i][j] = -1e30f;
        }
#pragma unroll
        for (int i = 0; i < 4; i++)
#pragma unroll
            for (int j = 0; j < 4; j++)
                Ss[(ty * 4 + i) * 65 + tx * 4 + j] = s[i][j];
        __syncthreads();

        const int r  = t >> 2;
        const int c0 = (t & 3) * 16;
        float pm = -1e30f;
#pragma unroll
        for (int c = 0; c < 16; c++) pm = fmaxf(pm, Ss[r * 65 + c0 + c]);
        red[r * 4 + (t & 3)] = pm;
        __syncthreads();

        if (t < 64) {
            float mold = m_s[t];
            float mnew = fmaxf(fmaxf(red[t * 4], red[t * 4 + 1]),
                               fmaxf(red[t * 4 + 2], red[t * 4 + 3]));
            mnew = fmaxf(mnew, mold);
            m_s[t]  = mnew;
            sc_s[t] = __expf(mold - mnew);
        }
        __syncthreads();

        {
            float mnew = m_s[r];
            float ps = 0.f;
#pragma unroll
            for (int c = 0; c < 16; c++) {
                float e = __expf(Ss[r * 65 + c0 + c] - mnew);
                Ss[r * 65 + c0 + c] = e;
                ps += e;
            }
            red[r * 4 + (t & 3)] = ps;
        }
        __syncthreads();

        if (t < 64)
            l_s[t] = l_s[t] * sc_s[t] +
                     red[t * 4] + red[t * 4 + 1] + red[t * 4 + 2] + red[t * 4 + 3];

#pragma unroll
        for (int i = 0; i < 4; i++) {
            float sc = sc_s[ty * 4 + i];
#pragma unroll
            for (int j = 0; j < 4; j++) acc[i][j] *= sc;
        }

#pragma unroll
        for (int kk = 0; kk < 64; kk++) {
            float p[4], v[4];
#pragma unroll
            for (int i = 0; i < 4; i++) p[i] = Ss[(ty * 4 + i) * 65 + kk];
#pragma unroll
            for (int j = 0; j < 4; j++) v[j] = Vs[kk * 65 + tx * 4 + j];
#pragma unroll
            for (int i = 0; i < 4; i++)
#pragma unroll
                for (int j = 0; j < 4; j++) acc[i][j] += p[i] * v[j];
        }
        __syncthreads();
    }

#pragma unroll
    for (int i = 0; i < 4; i++) {
        float inv = 1.f / l_s[ty * 4 + i];
        float4 o;
        o.x = acc[i][0] * inv;
        o.y = acc[i][1] * inv;
        o.z = acc[i][2] * inv;
        o.w = acc[i][3] * inv;
        *reinterpret_cast<float4*>(
            &out[(size_t)(b * T_ + q0 + ty * 4 + i) * C_ + h * DH_ + tx * 4]) = o;
    }
}

// ============================================================================
extern "C" void kernel_launch(void* const* d_in, const int* in_sizes, int n_in,
                              void* d_out, int out_size)
{
    const float* x     = (const float*)d_in[0];
    const float* w_qkv = (const float*)d_in[1];
    const float* w_out = (const float*)d_in[2];
    float*       out   = (float*)d_out;

    float *qkv, *att;
    __nv_bfloat16 *x3, *att3, *wqkv3, *wout3;
    cudaGetSymbolAddress((void**)&qkv,   g_qkv);
    cudaGetSymbolAddress((void**)&att,   g_att);
    cudaGetSymbolAddress((void**)&x3,    g_x3);
    cudaGetSymbolAddress((void**)&att3,  g_att3);
    cudaGetSymbolAddress((void**)&wqkv3, g_wqkv3);
    cudaGetSymbolAddress((void**)&wout3, g_wout3);

    cudaFuncSetAttribute(attn_kernel,
                         cudaFuncAttributeMaxDynamicSharedMemorySize, ATTN_SMEM);
    cudaFuncSetAttribute(gemm_mma_kernel,
                         cudaFuncAttributeMaxDynamicSharedMemorySize, GEMM_SMEM);

    // 0) split x and weights into 3-slab bf16
    {
        int n4 = (M_ * C_) / 4;
        split3_kernel<<<(n4 + 255) / 256, 256>>>(x, x3, C_, n4, 1);
        n4 = (N_QKV * C_) / 4;
        split3_kernel<<<(n4 + 255) / 256, 256>>>(w_qkv, wqkv3, C_, n4, 2);
        n4 = (C_ * C_) / 4;
        split3_kernel<<<(n4 + 255) / 256, 256>>>(w_out, wout3, C_, n4, 2);
    }
    // 1) QKV projection: [8192,3072bf16] x [3072,3072bf16]^T -> [8192,3072]f32
    {
        dim3 grid(N_QKV / BN, M_ / BM);
        gemm_mma_kernel<<<grid, 256, GEMM_SMEM>>>(x3, wqkv3, qkv, M_, N_QKV, K3_);
    }
    // 2) Causal attention -> g_att
    {
        dim3 grid(T_ / 64, B_ * H_);
        attn_kernel<<<grid, 256, ATTN_SMEM>>>(qkv, att);
    }
    // 3) split attention output, then output projection
    {
        int n4 = (M_ * C_) / 4;
        split3_kernel<<<(n4 + 255) / 256, 256>>>(att, att3, C_, n4, 1);
        dim3 grid(C_ / BN, M_ / BM);
        gemm_mma_kernel<<<grid, 256, GEMM_SMEM>>>(att3, wout3, out, M_, C_, K3_);
    }
}

// round 5
// speedup vs baseline: 2.2223x; 1.2429x over previous
#include <cuda_runtime.h>
#include <cuda_bf16.h>
#include <cstdint>

// ============================================================================
// Problem constants
// ============================================================================
constexpr int B_    = 4;
constexpr int T_    = 2048;
constexpr int C_    = 1024;
constexpr int H_    = 16;
constexpr int DH_   = 64;
constexpr int M_    = B_ * T_;        // 8192
constexpr int N_QKV = 3 * C_;         // 3072
constexpr int K3_   = 3 * C_;         // 3072
constexpr int BH_   = B_ * H_;        // 64

// ============================================================================
// Scratch (__device__ globals; no cudaMalloc allowed)
// ============================================================================
__device__ float          g_qkv[(size_t)M_ * N_QKV];
__device__ float          g_att[(size_t)M_ * C_];
__device__ __nv_bfloat16  g_x3[(size_t)M_ * K3_];
__device__ __nv_bfloat16  g_att3[(size_t)M_ * K3_];
__device__ __nv_bfloat16  g_wqkv3[(size_t)N_QKV * K3_];
__device__ __nv_bfloat16  g_wout3[(size_t)C_ * K3_];
// attention operands: [bh][T][64] for Q,K ; [bh][64][T] for V-transposed
__device__ __nv_bfloat16  g_qhi[(size_t)BH_ * T_ * DH_];
__device__ __nv_bfloat16  g_qlo[(size_t)BH_ * T_ * DH_];
__device__ __nv_bfloat16  g_khi[(size_t)BH_ * T_ * DH_];
__device__ __nv_bfloat16  g_klo[(size_t)BH_ * T_ * DH_];
__device__ __nv_bfloat16  g_vthi[(size_t)BH_ * DH_ * T_];
__device__ __nv_bfloat16  g_vtlo[(size_t)BH_ * DH_ * T_];

// ============================================================================
// PTX helpers (base-ISA only)
// ============================================================================
__device__ __forceinline__ uint32_t smem_to_u32(const void* smem_ptr) {
    uint32_t addr;
    asm("{ .reg .u64 tmp; cvta.to.shared.u64 tmp, %1; cvt.u32.u64 %0, tmp; }"
        : "=r"(addr) : "l"(smem_ptr));
    return addr;
}
__device__ __forceinline__ void ldsm_x4(uint32_t (&r)[4], uint32_t addr) {
    asm volatile("ldmatrix.sync.aligned.m8n8.x4.shared.b16 {%0,%1,%2,%3}, [%4];"
        : "=r"(r[0]), "=r"(r[1]), "=r"(r[2]), "=r"(r[3]) : "r"(addr));
}
__device__ __forceinline__ void ldsm_x2(uint32_t (&r)[2], uint32_t addr) {
    asm volatile("ldmatrix.sync.aligned.m8n8.x2.shared.b16 {%0,%1}, [%2];"
        : "=r"(r[0]), "=r"(r[1]) : "r"(addr));
}
__device__ __forceinline__ void mma_bf16(float (&d)[4],
                                         const uint32_t (&a)[4],
                                         const uint32_t (&b)[2]) {
    asm volatile(
        "mma.sync.aligned.m16n8k16.row.col.f32.bf16.bf16.f32 "
        "{%0,%1,%2,%3}, {%4,%5,%6,%7}, {%8,%9}, {%0,%1,%2,%3};"
        : "+f"(d[0]), "+f"(d[1]), "+f"(d[2]), "+f"(d[3])
        : "r"(a[0]), "r"(a[1]), "r"(a[2]), "r"(a[3]), "r"(b[0]), "r"(b[1]));
}
#define CP_ASYNC_16(dst_u32, src_ptr) \
    asm volatile("cp.async.cg.shared.global [%0], [%1], 16;" \
        :: "r"(dst_u32), "l"(src_ptr))
#define CP_ASYNC_COMMIT() asm volatile("cp.async.commit_group;" ::: "memory")
#define CP_ASYNC_WAIT_1() asm volatile("cp.async.wait_group 1;" ::: "memory")
#define CP_ASYNC_WAIT_0() asm volatile("cp.async.wait_group 0;" ::: "memory")

__device__ __forceinline__ uint32_t sw128(uint32_t off) {
    return off ^ ((off >> 3) & 0x70);
}
__device__ __forceinline__ uint32_t pack_bf2(float a, float b) {
    __nv_bfloat162 h = __floats2bfloat162_rn(a, b);
    return *reinterpret_cast<uint32_t*>(&h);
}

// ============================================================================
// Split fp32 -> 3-slab bf16 along K (hi|lo|hi for A, hi|hi|lo for B)
// ============================================================================
__global__ __launch_bounds__(256)
void split3_kernel(const float* __restrict__ in,
                   __nv_bfloat16* __restrict__ out3,
                   int K, int n4, int lo_slab)
{
    int i = blockIdx.x * blockDim.x + threadIdx.x;
    if (i >= n4) return;
    int e   = i * 4;
    int row = e / K;
    int col = e - row * K;
    float4 v = reinterpret_cast<const float4*>(in)[i];

    __nv_bfloat16 h0 = __float2bfloat16(v.x), h1 = __float2bfloat16(v.y);
    __nv_bfloat16 h2 = __float2bfloat16(v.z), h3 = __float2bfloat16(v.w);
    __nv_bfloat16 l0 = __float2bfloat16(v.x - __bfloat162float(h0));
    __nv_bfloat16 l1 = __float2bfloat16(v.y - __bfloat162float(h1));
    __nv_bfloat16 l2 = __float2bfloat16(v.z - __bfloat162float(h2));
    __nv_bfloat16 l3 = __float2bfloat16(v.w - __bfloat162float(h3));

    __nv_bfloat162 hA; hA.x = h0; hA.y = h1;
    __nv_bfloat162 hB; hB.x = h2; hB.y = h3;
    __nv_bfloat162 lA; lA.x = l0; lA.y = l1;
    __nv_bfloat162 lB; lB.x = l2; lB.y = l3;

    size_t base = (size_t)row * (3 * K) + col;
#pragma unroll
    for (int slab = 0; slab < 3; slab++) {
        __nv_bfloat162* p =
            reinterpret_cast<__nv_bfloat162*>(out3 + base + (size_t)slab * K);
        if (slab == lo_slab) { p[0] = lA; p[1] = lB; }
        else                 { p[0] = hA; p[1] = hB; }
    }
}

// ============================================================================
// bf16 NT GEMM via mma.sync (unchanged, verified in R4)
// ============================================================================
constexpr int BM = 128, BN = 128, BK = 64;
constexpr int TILEB     = BM * 128;
constexpr int GEMM_SMEM = 4 * TILEB;

__device__ __forceinline__ void gemm_issue_loads(
    const __nv_bfloat16* __restrict__ A, const __nv_bfloat16* __restrict__ Bm,
    int K, int m0, int n0, int kc, uint32_t abase, uint32_t bbase, int tid)
{
#pragma unroll
    for (int s = 0; s < 4; s++) {
        const int idx = tid + s * 256;
        const int r = idx >> 3;
        const int c = idx & 7;
        const uint32_t so = sw128((uint32_t)(r * 128 + c * 16));
        const __nv_bfloat16* ga = A  + (size_t)(m0 + r) * K + kc + c * 8;
        const __nv_bfloat16* gb = Bm + (size_t)(n0 + r) * K + kc + c * 8;
        CP_ASYNC_16(abase + so, ga);
        CP_ASYNC_16(bbase + so, gb);
    }
}

__global__ __launch_bounds__(256, 2)
void gemm_mma_kernel(const __nv_bfloat16* __restrict__ A,
                     const __nv_bfloat16* __restrict__ Bm,
                     float* __restrict__ Cm,
                     int M, int N, int K)
{
    extern __shared__ char sm[];
    const int tid  = threadIdx.x;
    const int wid  = tid >> 5;
    const int lane = tid & 31;
    const int m0 = blockIdx.y * BM;
    const int n0 = blockIdx.x * BN;
    const int wm = (wid & 1) * 64;
    const int wn = (wid >> 1) * 32;

    const uint32_t sbase = smem_to_u32(sm);

    float acc[4][4][4];
#pragma unroll
    for (int mi = 0; mi < 4; mi++)
#pragma unroll
        for (int ni = 0; ni < 4; ni++)
#pragma unroll
            for (int e = 0; e < 4; e++) acc[mi][ni][e] = 0.f;

    const int NC = K / BK;

    gemm_issue_loads(A, Bm, K, m0, n0, 0, sbase, sbase + TILEB, tid);
    CP_ASYNC_COMMIT();

    for (int ch = 0; ch < NC; ch++) {
        if (ch + 1 < NC) {
            const uint32_t nb = ((ch + 1) & 1) ? (uint32_t)(2 * TILEB) : 0u;
            gemm_issue_loads(A, Bm, K, m0, n0, (ch + 1) * BK,
                             sbase + nb, sbase + nb + TILEB, tid);
            CP_ASYNC_COMMIT();
            CP_ASYNC_WAIT_1();
        } else {
            CP_ASYNC_WAIT_0();
        }
        __syncthreads();

        const uint32_t abase = sbase + ((ch & 1) ? (uint32_t)(2 * TILEB) : 0u);
        const uint32_t bbase = abase + TILEB;

#pragma unroll
        for (int ks = 0; ks < 4; ks++) {
            uint32_t afr[4][4];
#pragma unroll
            for (int mi = 0; mi < 4; mi++) {
                const int row = wm + mi * 16 + (lane & 15);
                const uint32_t off =
                    sw128((uint32_t)(row * 128 + ks * 32 + ((lane >> 4) & 1) * 16));
                ldsm_x4(afr[mi], abase + off);
            }
            uint32_t bfr[4][2];
#pragma unroll
            for (int ni = 0; ni < 4; ni++) {
                const int row = wn + ni * 8 + (lane & 7);
                const uint32_t off =
                    sw128((uint32_t)(row * 128 + ks * 32 + ((lane >> 3) & 1) * 16));
                ldsm_x2(bfr[ni], bbase + off);
            }
#pragma unroll
            for (int mi = 0; mi < 4; mi++)
#pragma unroll
                for (int ni = 0; ni < 4; ni++)
                    mma_bf16(acc[mi][ni], afr[mi], bfr[ni]);
        }
        __syncthreads();
    }

    const int g  = lane >> 2;
    const int tg = lane & 3;
#pragma unroll
    for (int mi = 0; mi < 4; mi++) {
#pragma unroll
        for (int ni = 0; ni < 4; ni++) {
            const int row = m0 + wm + mi * 16 + g;
            const int col = n0 + wn + ni * 8 + tg * 2;
            float2 p0; p0.x = acc[mi][ni][0]; p0.y = acc[mi][ni][1];
            float2 p1; p1.x = acc[mi][ni][2]; p1.y = acc[mi][ni][3];
            *reinterpret_cast<float2*>(&Cm[(size_t)row * N + col])       = p0;
            *reinterpret_cast<float2*>(&Cm[(size_t)(row + 8) * N + col]) = p1;
        }
    }
}

// ============================================================================
// Attention preprocess: g_qkv fp32 -> Q(scaled) hi/lo, K hi/lo, V^T hi/lo
// grid (T/64, BH), 256 threads
// ============================================================================
__global__ __launch_bounds__(256)
void prep_attn_kernel(const float* __restrict__ qkv)
{
    __shared__ float vs[64][65];

    const int tid = threadIdx.x;
    const int bh  = blockIdx.y;
    const int b   = bh >> 4;
    const int h   = bh & 15;
    const int t0  = blockIdx.x * 64;

    const float scale = 0.125f;

    // Q and K: 64 rows x 64 cols, 1024 float4 per matrix, 4 per thread
#pragma unroll
    for (int it = 0; it < 4; it++) {
        const int idx = tid + it * 256;
        const int r  = idx >> 4;
        const int fc = (idx & 15) * 4;
        const size_t gq = (size_t)(b * T_ + t0 + r) * N_QKV + h * DH_ + fc;
        const size_t so = (size_t)(bh * T_ + t0 + r) * DH_ + fc;

        float4 qv = *reinterpret_cast<const float4*>(qkv + gq);
        qv.x *= scale; qv.y *= scale; qv.z *= scale; qv.w *= scale;
        float4 kv = *reinterpret_cast<const float4*>(qkv + gq + C_);
        float4 vv = *reinterpret_cast<const float4*>(qkv + gq + 2 * C_);

        // Q split
        {
            __nv_bfloat16 h0 = __float2bfloat16(qv.x), h1 = __float2bfloat16(qv.y);
            __nv_bfloat16 h2 = __float2bfloat16(qv.z), h3 = __float2bfloat16(qv.w);
            __nv_bfloat162 ha; ha.x = h0; ha.y = h1;
            __nv_bfloat162 hb; hb.x = h2; hb.y = h3;
            __nv_bfloat162 la; la.x = __float2bfloat16(qv.x - __bfloat162float(h0));
                               la.y = __float2bfloat16(qv.y - __bfloat162float(h1));
            __nv_bfloat162 lb; lb.x = __float2bfloat16(qv.z - __bfloat162float(h2));
                               lb.y = __float2bfloat16(qv.w - __bfloat162float(h3));
            reinterpret_cast<__nv_bfloat162*>(g_qhi + so)[0] = ha;
            reinterpret_cast<__nv_bfloat162*>(g_qhi + so)[1] = hb;
            reinterpret_cast<__nv_bfloat162*>(g_qlo + so)[0] = la;
            reinterpret_cast<__nv_bfloat162*>(g_qlo + so)[1] = lb;
        }
        // K split
        {
            __nv_bfloat16 h0 = __float2bfloat16(kv.x), h1 = __float2bfloat16(kv.y);
            __nv_bfloat16 h2 = __float2bfloat16(kv.z), h3 = __float2bfloat16(kv.w);
            __nv_bfloat162 ha; ha.x = h0; ha.y = h1;
            __nv_bfloat162 hb; hb.x = h2; hb.y = h3;
            __nv_bfloat162 la; la.x = __float2bfloat16(kv.x - __bfloat162float(h0));
                               la.y = __float2bfloat16(kv.y - __bfloat162float(h1));
            __nv_bfloat162 lb; lb.x = __float2bfloat16(kv.z - __bfloat162float(h2));
                               lb.y = __float2bfloat16(kv.w - __bfloat162float(h3));
            reinterpret_cast<__nv_bfloat162*>(g_khi + so)[0] = ha;
            reinterpret_cast<__nv_bfloat162*>(g_khi + so)[1] = hb;
            reinterpret_cast<__nv_bfloat162*>(g_klo + so)[0] = la;
            reinterpret_cast<__nv_bfloat162*>(g_klo + so)[1] = lb;
        }
        // V -> smem staging
        vs[r][fc + 0] = vv.x;
        vs[r][fc + 1] = vv.y;
        vs[r][fc + 2] = vv.z;
        vs[r][fc + 3] = vv.w;
    }
    __syncthreads();

    // write V transposed: row = d (64), cols = t (64)
    {
        const int d  = tid >> 2;          // 0..63
        const int tp = (tid & 3) * 16;    // 16 t-values per thread
        const size_t vbase = (size_t)(bh * DH_ + d) * T_ + t0 + tp;
#pragma unroll
        for (int j = 0; j < 8; j++) {
            float a = vs[tp + j * 2 + 0][d];
            float c = vs[tp + j * 2 + 1][d];
            __nv_bfloat16 ha = __float2bfloat16(a), hc = __float2bfloat16(c);
            __nv_bfloat162 hp; hp.x = ha; hp.y = hc;
            __nv_bfloat162 lp;
            lp.x = __float2bfloat16(a - __bfloat162float(ha));
            lp.y = __float2bfloat16(c - __bfloat162float(hc));
            *reinterpret_cast<__nv_bfloat162*>(g_vthi + vbase + j * 2) = hp;
            *reinterpret_cast<__nv_bfloat162*>(g_vtlo + vbase + j * 2) = lp;
        }
    }
}

// ============================================================================
// Tensor-core flash attention (causal).
// grid: (T/128, BH), 256 threads = 8 warps x 16 q-rows. K/V tile = 64 keys.
// smem: Qhi/Qlo 16KB each + Khi/Klo/Vhi/Vlo 8KB each = 64KB.
// ============================================================================
constexpr int ATT_SMEM = 64 * 1024;
constexpr uint32_t OQHI = 0, OQLO = 16384, OKHI = 32768, OKLO = 40960,
                   OVHI = 49152, OVLO = 57344;

__global__ __launch_bounds__(256, 2)
void attn_mma_kernel(float* __restrict__ out)
{
    extern __shared__ char sm[];
    const uint32_t sb = smem_to_u32(sm);

    const int tid  = threadIdx.x;
    const int w    = tid >> 5;
    const int lane = tid & 31;
    const int g    = lane >> 2;
    const int tq   = lane & 3;

    const int bh = blockIdx.y;
    const int b  = bh >> 4;
    const int h  = bh & 15;
    const int qt = gridDim.x - 1 - blockIdx.x;   // heavy tiles first
    const int q0 = qt * 128;

    // ---- load Q tile (128 rows x 64 bf16, hi+lo) via cp.async
    {
        const __nv_bfloat16* qh = g_qhi + (size_t)(bh * T_ + q0) * DH_;
        const __nv_bfloat16* ql = g_qlo + (size_t)(bh * T_ + q0) * DH_;
#pragma unroll
        for (int it = 0; it < 4; it++) {
            const int idx = tid + it * 256;   // 0..1023
            const int r = idx >> 3;
            const int c = idx & 7;
            const uint32_t so = sw128((uint32_t)(r * 128 + c * 16));
            CP_ASYNC_16(sb + OQHI + so, qh + (size_t)r * DH_ + c * 8);
            CP_ASYNC_16(sb + OQLO + so, ql + (size_t)r * DH_ + c * 8);
        }
        CP_ASYNC_COMMIT();
    }

    float o[8][4];
#pragma unroll
    for (int ni = 0; ni < 8; ni++)
#pragma unroll
        for (int e = 0; e < 4; e++) o[ni][e] = 0.f;
    float m0 = -1e30f, m1 = -1e30f, l0 = 0.f, l1 = 0.f;

    const int row0 = q0 + 16 * w + g;     // thread's first q row
    const int kt_max = (q0 + 127) >> 6;

    const __nv_bfloat16* khg = g_khi + (size_t)bh * T_ * DH_;
    const __nv_bfloat16* klg = g_klo + (size_t)bh * T_ * DH_;
    const __nv_bfloat16* vhg = g_vthi + (size_t)bh * DH_ * T_;
    const __nv_bfloat16* vlg = g_vtlo + (size_t)bh * DH_ * T_;

    for (int kt = 0; kt <= kt_max; kt++) {
        const int k0 = kt * 64;

        // ---- load K (hi,lo) [64 x 64] and Vt (hi,lo) [64 d x 64 keys]
#pragma unroll
        for (int it = 0; it < 2; it++) {
            const int idx = tid + it * 256;   // 0..511
            const int r = idx >> 3;
            const int c = idx & 7;
            const uint32_t so = sw128((uint32_t)(r * 128 + c * 16));
            CP_ASYNC_16(sb + OKHI + so, khg + (size_t)(k0 + r) * DH_ + c * 8);
            CP_ASYNC_16(sb + OKLO + so, klg + (size_t)(k0 + r) * DH_ + c * 8);
            CP_ASYNC_16(sb + OVHI + so, vhg + (size_t)r * T_ + k0 + c * 8);
            CP_ASYNC_16(sb + OVLO + so, vlg + (size_t)r * T_ + k0 + c * 8);
        }
        CP_ASYNC_COMMIT();
        CP_ASYNC_WAIT_0();
        __syncthreads();

        const bool active = (k0 <= q0 + 16 * w + 15);
        if (active) {
            // ---- S = Q K^T (3 bf16 products, fp32 accum)
            float s[8][4];
#pragma unroll
            for (int ni = 0; ni < 8; ni++)
#pragma unroll
                for (int e = 0; e < 4; e++) s[ni][e] = 0.f;

#pragma unroll
            for (int ks = 0; ks < 4; ks++) {
                uint32_t aqh[4], aql[4];
                {
                    const int qr = 16 * w + (lane & 15);
                    const uint32_t off = sw128(
                        (uint32_t)(qr * 128 + ks * 32 + ((lane >> 4) & 1) * 16));
                    ldsm_x4(aqh, sb + OQHI + off);
                    ldsm_x4(aql, sb + OQLO + off);
                }
                uint32_t bkh[8][2], bkl[8][2];
#pragma unroll
                for (int p = 0; p < 4; p++) {
                    const int kr = p * 16 + ((lane >> 4) & 1) * 8 + (lane & 7);
                    const uint32_t off = sw128(
                        (uint32_t)(kr * 128 + ks * 32 + ((lane >> 3) & 1) * 16));
                    uint32_t r4[4];
                    ldsm_x4(r4, sb + OKHI + off);
                    bkh[2 * p][0] = r4[0]; bkh[2 * p][1] = r4[1];
                    bkh[2 * p + 1][0] = r4[2]; bkh[2 * p + 1][1] = r4[3];
                    ldsm_x4(r4, sb + OKLO + off);
                    bkl[2 * p][0] = r4[0]; bkl[2 * p][1] = r4[1];
                    bkl[2 * p + 1][0] = r4[2]; bkl[2 * p + 1][1] = r4[3];
                }
#pragma unroll
                for (int ni = 0; ni < 8; ni++) {
                    mma_bf16(s[ni], aqh, bkh[ni]);
                    mma_bf16(s[ni], aqh, bkl[ni]);
                    mma_bf16(s[ni], aql, bkh[ni]);
                }
            }

            // ---- causal mask (elementwise) when tile overlaps diagonal
            if (k0 + 63 > q0 + 16 * w) {
#pragma unroll
                for (int ni = 0; ni < 8; ni++) {
                    const int kb = k0 + 8 * ni + 2 * tq;
                    if (kb     > row0)     s[ni][0] = -1e30f;
                    if (kb + 1 > row0)     s[ni][1] = -1e30f;
                    if (kb     > row0 + 8) s[ni][2] = -1e30f;
                    if (kb + 1 > row0 + 8) s[ni][3] = -1e30f;
                }
            }

            // ---- online softmax
            float mx0 = -1e30f, mx1 = -1e30f;
#pragma unroll
            for (int ni = 0; ni < 8; ni++) {
                mx0 = fmaxf(mx0, fmaxf(s[ni][0], s[ni][1]));
                mx1 = fmaxf(mx1, fmaxf(s[ni][2], s[ni][3]));
            }
            mx0 = fmaxf(mx0, __shfl_xor_sync(0xffffffffu, mx0, 1));
            mx0 = fmaxf(mx0, __shfl_xor_sync(0xffffffffu, mx0, 2));
            mx1 = fmaxf(mx1, __shfl_xor_sync(0xffffffffu, mx1, 1));
            mx1 = fmaxf(mx1, __shfl_xor_sync(0xffffffffu, mx1, 2));

            const float mn0 = fmaxf(m0, mx0);
            const float mn1 = fmaxf(m1, mx1);
            const float sc0 = __expf(m0 - mn0);
            const float sc1 = __expf(m1 - mn1);
            m0 = mn0; m1 = mn1;
            l0 *= sc0; l1 *= sc1;
#pragma unroll
            for (int ni = 0; ni < 8; ni++) {
                o[ni][0] *= sc0; o[ni][1] *= sc0;
                o[ni][2] *= sc1; o[ni][3] *= sc1;
            }

            // ---- P = exp(S - m); split to bf16 hi/lo fragments
            uint32_t pH01[8], pH23[8], pL01[8], pL23[8];
#pragma unroll
            for (int ni = 0; ni < 8; ni++) {
                float p0 = __expf(s[ni][0] - mn0);
                float p1 = __expf(s[ni][1] - mn0);
                float p2 = __expf(s[ni][2] - mn1);
                float p3 = __expf(s[ni][3] - mn1);
                l0 += p0 + p1;
                l1 += p2 + p3;
                __nv_bfloat162 h01 = __floats2bfloat162_rn(p0, p1);
                __nv_bfloat162 h23 = __floats2bfloat162_rn(p2, p3);
                pH01[ni] = *reinterpret_cast<uint32_t*>(&h01);
                pH23[ni] = *reinterpret_cast<uint32_t*>(&h23);
                __nv_bfloat162 l01 = __floats2bfloat162_rn(
                    p0 - __bfloat162float(h01.x), p1 - __bfloat162float(h01.y));
                __nv_bfloat162 l23 = __floats2bfloat162_rn(
                    p2 - __bfloat162float(h23.x), p3 - __bfloat162float(h23.y));
                pL01[ni] = *reinterpret_cast<uint32_t*>(&l01);
                pL23[ni] = *reinterpret_cast<uint32_t*>(&l23);
            }

            // ---- O += P V  (3 products)
#pragma unroll
            for (int kg = 0; kg < 4; kg++) {
                uint32_t aph[4], apl[4];
                aph[0] = pH01[2 * kg];     aph[1] = pH23[2 * kg];
                aph[2] = pH01[2 * kg + 1]; aph[3] = pH23[2 * kg + 1];
                apl[0] = pL01[2 * kg];     apl[1] = pL23[2 * kg];
                apl[2] = pL01[2 * kg + 1]; apl[3] = pL23[2 * kg + 1];

                uint32_t bvh[8][2], bvl[8][2];
#pragma unroll
                for (int p = 0; p < 4; p++) {
                    const int dr = p * 16 + ((lane >> 4) & 1) * 8 + (lane & 7);
                    const uint32_t off = sw128(
                        (uint32_t)(dr * 128 + kg * 32 + ((lane >> 3) & 1) * 16));
                    uint32_t r4[4];
                    ldsm_x4(r4, sb + OVHI + off);
                    bvh[2 * p][0] = r4[0]; bvh[2 * p][1] = r4[1];
                    bvh[2 * p + 1][0] = r4[2]; bvh[2 * p + 1][1] = r4[3];
                    ldsm_x4(r4, sb + OVLO + off);
                    bvl[2 * p][0] = r4[0]; bvl[2 * p][1] = r4[1];
                    bvl[2 * p + 1][0] = r4[2]; bvl[2 * p + 1][1] = r4[3];
                }
#pragma unroll
                for (int ni = 0; ni < 8; ni++) {
                    mma_bf16(o[ni], aph, bvh[ni]);
                    mma_bf16(o[ni], apl, bvh[ni]);
                    mma_bf16(o[ni], aph, bvl[ni]);
                }
            }
        }
        __syncthreads();
    }

    // ---- finalize: quad-reduce l, normalize, store fp32 to g_att layout
    l0 += __shfl_xor_sync(0xffffffffu, l0, 1);
    l0 += __shfl_xor_sync(0xffffffffu, l0, 2);
    l1 += __shfl_xor_sync(0xffffffffu, l1, 1);
    l1 += __shfl_xor_sync(0xffffffffu, l1, 2);
    const float inv0 = 1.f / l0;
    const float inv1 = 1.f / l1;

    float* orow0 = out + (size_t)(b * T_ + row0) * C_ + h * DH_;
    float* orow1 = orow0 + (size_t)8 * C_;
#pragma unroll
    for (int ni = 0; ni < 8; ni++) {
        const int col = 8 * ni + 2 * tq;
        float2 v0; v0.x = o[ni][0] * inv0; v0.y = o[ni][1] * inv0;
        float2 v1; v1.x = o[ni][2] * inv1; v1.y = o[ni][3] * inv1;
        *reinterpret_cast<float2*>(orow0 + col) = v0;
        *reinterpret_cast<float2*>(orow1 + col) = v1;
    }
}

// ============================================================================
extern "C" void kernel_launch(void* const* d_in, const int* in_sizes, int n_in,
                              void* d_out, int out_size)
{
    const float* x     = (const float*)d_in[0];
    const float* w_qkv = (const float*)d_in[1];
    const float* w_out = (const float*)d_in[2];
    float*       out   = (float*)d_out;

    float *qkv, *att;
    __nv_bfloat16 *x3, *att3, *wqkv3, *wout3;
    cudaGetSymbolAddress((void**)&qkv,   g_qkv);
    cudaGetSymbolAddress((void**)&att,   g_att);
    cudaGetSymbolAddress((void**)&x3,    g_x3);
    cudaGetSymbolAddress((void**)&att3,  g_att3);
    cudaGetSymbolAddress((void**)&wqkv3, g_wqkv3);
    cudaGetSymbolAddress((void**)&wout3, g_wout3);

    cudaFuncSetAttribute(gemm_mma_kernel,
                         cudaFuncAttributeMaxDynamicSharedMemorySize, GEMM_SMEM);
    cudaFuncSetAttribute(attn_mma_kernel,
                         cudaFuncAttributeMaxDynamicSharedMemorySize, ATT_SMEM);

    // 0) split x and weights into 3-slab bf16
    {
        int n4 = (M_ * C_) / 4;
        split3_kernel<<<(n4 + 255) / 256, 256>>>(x, x3, C_, n4, 1);
        n4 = (N_QKV * C_) / 4;
        split3_kernel<<<(n4 + 255) / 256, 256>>>(w_qkv, wqkv3, C_, n4, 2);
        n4 = (C_ * C_) / 4;
        split3_kernel<<<(n4 + 255) / 256, 256>>>(w_out, wout3, C_, n4, 2);
    }
    // 1) QKV projection
    {
        dim3 grid(N_QKV / BN, M_ / BM);
        gemm_mma_kernel<<<grid, 256, GEMM_SMEM>>>(x3, wqkv3, qkv, M_, N_QKV, K3_);
    }
    // 2) attention preprocess (split + V transpose)
    {
        dim3 grid(T_ / 64, BH_);
        prep_attn_kernel<<<grid, 256>>>(qkv);
    }
    // 3) tensor-core causal attention -> g_att
    {
        dim3 grid(T_ / 128, BH_);
        attn_mma_kernel<<<grid, 256, ATT_SMEM>>>(att);
    }
    // 4) split attention output, output projection
    {
        int n4 = (M_ * C_) / 4;
        split3_kernel<<<(n4 + 255) / 256, 256>>>(att, att3, C_, n4, 1);
        dim3 grid(C_ / BN, M_ / BM);
        gemm_mma_kernel<<<grid, 256, GEMM_SMEM>>>(att3, wout3, out, M_, C_, K3_);
    }
}

// round 6
// speedup vs baseline: 2.2469x; 1.0111x over previous
#include <cuda_runtime.h>
#include <cuda_bf16.h>
#include <cstdint>

// ============================================================================
// Problem constants
// ============================================================================
constexpr int B_    = 4;
constexpr int T_    = 2048;
constexpr int C_    = 1024;
constexpr int H_    = 16;
constexpr int DH_   = 64;
constexpr int M_    = B_ * T_;        // 8192
constexpr int N_QKV = 3 * C_;         // 3072
constexpr int K3_   = 3 * C_;         // 3072
constexpr int BH_   = B_ * H_;        // 64

// ============================================================================
// Scratch (__device__ globals; no cudaMalloc allowed)
// ============================================================================
__device__ float          g_qkv[(size_t)M_ * N_QKV];
__device__ float          g_att[(size_t)M_ * C_];
__device__ __nv_bfloat16  g_x3[(size_t)M_ * K3_];
__device__ __nv_bfloat16  g_att3[(size_t)M_ * K3_];
__device__ __nv_bfloat16  g_wqkv3[(size_t)N_QKV * K3_];
__device__ __nv_bfloat16  g_wout3[(size_t)C_ * K3_];
__device__ __nv_bfloat16  g_qhi[(size_t)BH_ * T_ * DH_];
__device__ __nv_bfloat16  g_qlo[(size_t)BH_ * T_ * DH_];
__device__ __nv_bfloat16  g_khi[(size_t)BH_ * T_ * DH_];
__device__ __nv_bfloat16  g_klo[(size_t)BH_ * T_ * DH_];
__device__ __nv_bfloat16  g_vthi[(size_t)BH_ * DH_ * T_];
__device__ __nv_bfloat16  g_vtlo[(size_t)BH_ * DH_ * T_];

// ============================================================================
// PTX helpers (base-ISA only)
// ============================================================================
__device__ __forceinline__ uint32_t smem_to_u32(const void* smem_ptr) {
    uint32_t addr;
    asm("{ .reg .u64 tmp; cvta.to.shared.u64 tmp, %1; cvt.u32.u64 %0, tmp; }"
        : "=r"(addr) : "l"(smem_ptr));
    return addr;
}
__device__ __forceinline__ void ldsm_x4(uint32_t (&r)[4], uint32_t addr) {
    asm volatile("ldmatrix.sync.aligned.m8n8.x4.shared.b16 {%0,%1,%2,%3}, [%4];"
        : "=r"(r[0]), "=r"(r[1]), "=r"(r[2]), "=r"(r[3]) : "r"(addr));
}
__device__ __forceinline__ void ldsm_x2(uint32_t (&r)[2], uint32_t addr) {
    asm volatile("ldmatrix.sync.aligned.m8n8.x2.shared.b16 {%0,%1}, [%2];"
        : "=r"(r[0]), "=r"(r[1]) : "r"(addr));
}
__device__ __forceinline__ void mma_bf16(float (&d)[4],
                                         const uint32_t (&a)[4],
                                         const uint32_t (&b)[2]) {
    asm volatile(
        "mma.sync.aligned.m16n8k16.row.col.f32.bf16.bf16.f32 "
        "{%0,%1,%2,%3}, {%4,%5,%6,%7}, {%8,%9}, {%0,%1,%2,%3};"
        : "+f"(d[0]), "+f"(d[1]), "+f"(d[2]), "+f"(d[3])
        : "r"(a[0]), "r"(a[1]), "r"(a[2]), "r"(a[3]), "r"(b[0]), "r"(b[1]));
}
#define CP_ASYNC_16(dst_u32, src_ptr) \
    asm volatile("cp.async.cg.shared.global [%0], [%1], 16;" \
        :: "r"(dst_u32), "l"(src_ptr))
#define CP_ASYNC_COMMIT() asm volatile("cp.async.commit_group;" ::: "memory")
#define CP_ASYNC_WAIT_2() asm volatile("cp.async.wait_group 2;" ::: "memory")
#define CP_ASYNC_WAIT_1() asm volatile("cp.async.wait_group 1;" ::: "memory")
#define CP_ASYNC_WAIT_0() asm volatile("cp.async.wait_group 0;" ::: "memory")

__device__ __forceinline__ uint32_t sw128(uint32_t off) {
    return off ^ ((off >> 3) & 0x70);
}

// ============================================================================
// Split fp32 -> 3-slab bf16 along K (hi|lo|hi for A, hi|hi|lo for B)
// ============================================================================
__global__ __launch_bounds__(256)
void split3_kernel(const float* __restrict__ in,
                   __nv_bfloat16* __restrict__ out3,
                   int K, int n4, int lo_slab)
{
    int i = blockIdx.x * blockDim.x + threadIdx.x;
    if (i >= n4) return;
    int e   = i * 4;
    int row = e / K;
    int col = e - row * K;
    float4 v = reinterpret_cast<const float4*>(in)[i];

    __nv_bfloat16 h0 = __float2bfloat16(v.x), h1 = __float2bfloat16(v.y);
    __nv_bfloat16 h2 = __float2bfloat16(v.z), h3 = __float2bfloat16(v.w);
    __nv_bfloat16 l0 = __float2bfloat16(v.x - __bfloat162float(h0));
    __nv_bfloat16 l1 = __float2bfloat16(v.y - __bfloat162float(h1));
    __nv_bfloat16 l2 = __float2bfloat16(v.z - __bfloat162float(h2));
    __nv_bfloat16 l3 = __float2bfloat16(v.w - __bfloat162float(h3));

    __nv_bfloat162 hA; hA.x = h0; hA.y = h1;
    __nv_bfloat162 hB; hB.x = h2; hB.y = h3;
    __nv_bfloat162 lA; lA.x = l0; lA.y = l1;
    __nv_bfloat162 lB; lB.x = l2; lB.y = l3;

    size_t base = (size_t)row * (3 * K) + col;
#pragma unroll
    for (int slab = 0; slab < 3; slab++) {
        __nv_bfloat162* p =
            reinterpret_cast<__nv_bfloat162*>(out3 + base + (size_t)slab * K);
        if (slab == lo_slab) { p[0] = lA; p[1] = lB; }
        else                 { p[0] = hA; p[1] = hB; }
    }
}

// ============================================================================
// bf16 NT GEMM via mma.sync — 3-stage cp.async pipeline.
// Tile 128x128, BK=64, 256 threads (8 warps x 64x32).
// smem: 3 stages x (A 16KB + B 16KB) = 96KB.
// ============================================================================
constexpr int BM = 128, BN = 128, BK = 64;
constexpr int TILEB     = BM * 128;            // 16 KB
constexpr int STAGEB    = 2 * TILEB;           // 32 KB (A+B)
constexpr int GEMM_SMEM = 3 * STAGEB;          // 96 KB

__device__ __forceinline__ void gemm_issue_loads(
    const __nv_bfloat16* __restrict__ A, const __nv_bfloat16* __restrict__ Bm,
    int K, int m0, int n0, int kc, uint32_t abase, uint32_t bbase, int tid)
{
#pragma unroll
    for (int s = 0; s < 4; s++) {
        const int idx = tid + s * 256;
        const int r = idx >> 3;
        const int c = idx & 7;
        const uint32_t so = sw128((uint32_t)(r * 128 + c * 16));
        const __nv_bfloat16* ga = A  + (size_t)(m0 + r) * K + kc + c * 8;
        const __nv_bfloat16* gb = Bm + (size_t)(n0 + r) * K + kc + c * 8;
        CP_ASYNC_16(abase + so, ga);
        CP_ASYNC_16(bbase + so, gb);
    }
}

__global__ __launch_bounds__(256, 2)
void gemm_mma_kernel(const __nv_bfloat16* __restrict__ A,
                     const __nv_bfloat16* __restrict__ Bm,
                     float* __restrict__ Cm,
                     int M, int N, int K)
{
    extern __shared__ char sm[];
    const int tid  = threadIdx.x;
    const int wid  = tid >> 5;
    const int lane = tid & 31;
    const int m0 = blockIdx.y * BM;
    const int n0 = blockIdx.x * BN;
    const int wm = (wid & 1) * 64;
    const int wn = (wid >> 1) * 32;

    const uint32_t sbase = smem_to_u32(sm);

    float acc[4][4][4];
#pragma unroll
    for (int mi = 0; mi < 4; mi++)
#pragma unroll
        for (int ni = 0; ni < 4; ni++)
#pragma unroll
            for (int e = 0; e < 4; e++) acc[mi][ni][e] = 0.f;

    const int NC = K / BK;

    // prologue: issue stages 0 and 1
    gemm_issue_loads(A, Bm, K, m0, n0, 0, sbase, sbase + TILEB, tid);
    CP_ASYNC_COMMIT();
    if (NC > 1) {
        gemm_issue_loads(A, Bm, K, m0, n0, BK,
                         sbase + STAGEB, sbase + STAGEB + TILEB, tid);
    }
    CP_ASYNC_COMMIT();

    int stage = 0;
    for (int ch = 0; ch < NC; ch++) {
        if (ch + 2 < NC) {
            const int ns = (ch + 2) % 3;
            gemm_issue_loads(A, Bm, K, m0, n0, (ch + 2) * BK,
                             sbase + ns * STAGEB, sbase + ns * STAGEB + TILEB, tid);
            CP_ASYNC_COMMIT();
            CP_ASYNC_WAIT_2();
        } else if (ch + 1 < NC) {
            CP_ASYNC_WAIT_1();
        } else {
            CP_ASYNC_WAIT_0();
        }
        __syncthreads();

        const uint32_t abase = sbase + stage * STAGEB;
        const uint32_t bbase = abase + TILEB;

#pragma unroll
        for (int ks = 0; ks < 4; ks++) {
            uint32_t afr[4][4];
#pragma unroll
            for (int mi = 0; mi < 4; mi++) {
                const int row = wm + mi * 16 + (lane & 15);
                const uint32_t off =
                    sw128((uint32_t)(row * 128 + ks * 32 + ((lane >> 4) & 1) * 16));
                ldsm_x4(afr[mi], abase + off);
            }
            uint32_t bfr[4][2];
#pragma unroll
            for (int ni = 0; ni < 4; ni++) {
                const int row = wn + ni * 8 + (lane & 7);
                const uint32_t off =
                    sw128((uint32_t)(row * 128 + ks * 32 + ((lane >> 3) & 1) * 16));
                ldsm_x2(bfr[ni], bbase + off);
            }
#pragma unroll
            for (int mi = 0; mi < 4; mi++)
#pragma unroll
                for (int ni = 0; ni < 4; ni++)
                    mma_bf16(acc[mi][ni], afr[mi], bfr[ni]);
        }
        __syncthreads();
        stage = (stage + 1) % 3;
    }

    const int g  = lane >> 2;
    const int tg = lane & 3;
#pragma unroll
    for (int mi = 0; mi < 4; mi++) {
#pragma unroll
        for (int ni = 0; ni < 4; ni++) {
            const int row = m0 + wm + mi * 16 + g;
            const int col = n0 + wn + ni * 8 + tg * 2;
            float2 p0; p0.x = acc[mi][ni][0]; p0.y = acc[mi][ni][1];
            float2 p1; p1.x = acc[mi][ni][2]; p1.y = acc[mi][ni][3];
            *reinterpret_cast<float2*>(&Cm[(size_t)row * N + col])       = p0;
            *reinterpret_cast<float2*>(&Cm[(size_t)(row + 8) * N + col]) = p1;
        }
    }
}

// ============================================================================
// Attention preprocess: g_qkv fp32 -> Q(scaled) hi/lo, K hi/lo, V^T hi/lo
// ============================================================================
__global__ __launch_bounds__(256)
void prep_attn_kernel(const float* __restrict__ qkv)
{
    __shared__ float vs[64][65];

    const int tid = threadIdx.x;
    const int bh  = blockIdx.y;
    const int b   = bh >> 4;
    const int h   = bh & 15;
    const int t0  = blockIdx.x * 64;

    const float scale = 0.125f;

#pragma unroll
    for (int it = 0; it < 4; it++) {
        const int idx = tid + it * 256;
        const int r  = idx >> 4;
        const int fc = (idx & 15) * 4;
        const size_t gq = (size_t)(b * T_ + t0 + r) * N_QKV + h * DH_ + fc;
        const size_t so = (size_t)(bh * T_ + t0 + r) * DH_ + fc;

        float4 qv = *reinterpret_cast<const float4*>(qkv + gq);
        qv.x *= scale; qv.y *= scale; qv.z *= scale; qv.w *= scale;
        float4 kv = *reinterpret_cast<const float4*>(qkv + gq + C_);
        float4 vv = *reinterpret_cast<const float4*>(qkv + gq + 2 * C_);

        {
            __nv_bfloat16 h0 = __float2bfloat16(qv.x), h1 = __float2bfloat16(qv.y);
            __nv_bfloat16 h2 = __float2bfloat16(qv.z), h3 = __float2bfloat16(qv.w);
            __nv_bfloat162 ha; ha.x = h0; ha.y = h1;
            __nv_bfloat162 hb; hb.x = h2; hb.y = h3;
            __nv_bfloat162 la; la.x = __float2bfloat16(qv.x - __bfloat162float(h0));
                               la.y = __float2bfloat16(qv.y - __bfloat162float(h1));
            __nv_bfloat162 lb; lb.x = __float2bfloat16(qv.z - __bfloat162float(h2));
                               lb.y = __float2bfloat16(qv.w - __bfloat162float(h3));
            reinterpret_cast<__nv_bfloat162*>(g_qhi + so)[0] = ha;
            reinterpret_cast<__nv_bfloat162*>(g_qhi + so)[1] = hb;
            reinterpret_cast<__nv_bfloat162*>(g_qlo + so)[0] = la;
            reinterpret_cast<__nv_bfloat162*>(g_qlo + so)[1] = lb;
        }
        {
            __nv_bfloat16 h0 = __float2bfloat16(kv.x), h1 = __float2bfloat16(kv.y);
            __nv_bfloat16 h2 = __float2bfloat16(kv.z), h3 = __float2bfloat16(kv.w);
            __nv_bfloat162 ha; ha.x = h0; ha.y = h1;
            __nv_bfloat162 hb; hb.x = h2; hb.y = h3;
            __nv_bfloat162 la; la.x = __float2bfloat16(kv.x - __bfloat162float(h0));
                               la.y = __float2bfloat16(kv.y - __bfloat162float(h1));
            __nv_bfloat162 lb; lb.x = __float2bfloat16(kv.z - __bfloat162float(h2));
                               lb.y = __float2bfloat16(kv.w - __bfloat162float(h3));
            reinterpret_cast<__nv_bfloat162*>(g_khi + so)[0] = ha;
            reinterpret_cast<__nv_bfloat162*>(g_khi + so)[1] = hb;
            reinterpret_cast<__nv_bfloat162*>(g_klo + so)[0] = la;
            reinterpret_cast<__nv_bfloat162*>(g_klo + so)[1] = lb;
        }
        vs[r][fc + 0] = vv.x;
        vs[r][fc + 1] = vv.y;
        vs[r][fc + 2] = vv.z;
        vs[r][fc + 3] = vv.w;
    }
    __syncthreads();

    {
        const int d  = tid >> 2;
        const int tp = (tid & 3) * 16;
        const size_t vbase = (size_t)(bh * DH_ + d) * T_ + t0 + tp;
#pragma unroll
        for (int j = 0; j < 8; j++) {
            float a = vs[tp + j * 2 + 0][d];
            float c = vs[tp + j * 2 + 1][d];
            __nv_bfloat16 ha = __float2bfloat16(a), hc = __float2bfloat16(c);
            __nv_bfloat162 hp; hp.x = ha; hp.y = hc;
            __nv_bfloat162 lp;
            lp.x = __float2bfloat16(a - __bfloat162float(ha));
            lp.y = __float2bfloat16(c - __bfloat162float(hc));
            *reinterpret_cast<__nv_bfloat162*>(g_vthi + vbase + j * 2) = hp;
            *reinterpret_cast<__nv_bfloat162*>(g_vtlo + vbase + j * 2) = lp;
        }
    }
}

// ============================================================================
// Tensor-core flash attention (causal), double-buffered K/V.
// grid: (T/128, BH), 256 threads. K/V tile = 64 keys.
// smem: Q hi/lo 32KB + 2 stages x (Khi,Klo,Vhi,Vlo 8KB each = 32KB) = 96KB.
// ============================================================================
constexpr int ATT_SMEM = 96 * 1024;
constexpr uint32_t OQHI = 0, OQLO = 16384, OKV = 32768, KVSTAGE = 32768;
// within a KV stage: KHI +0, KLO +8192, VHI +16384, VLO +24576

__global__ __launch_bounds__(256, 2)
void attn_mma_kernel(float* __restrict__ out)
{
    extern __shared__ char sm[];
    const uint32_t sb = smem_to_u32(sm);

    const int tid  = threadIdx.x;
    const int w    = tid >> 5;
    const int lane = tid & 31;
    const int g    = lane >> 2;
    const int tq   = lane & 3;

    const int bh = blockIdx.y;
    const int b  = bh >> 4;
    const int h  = bh & 15;
    const int qt = gridDim.x - 1 - blockIdx.x;   // heavy tiles first
    const int q0 = qt * 128;

    const __nv_bfloat16* khg = g_khi + (size_t)bh * T_ * DH_;
    const __nv_bfloat16* klg = g_klo + (size_t)bh * T_ * DH_;
    const __nv_bfloat16* vhg = g_vthi + (size_t)bh * DH_ * T_;
    const __nv_bfloat16* vlg = g_vtlo + (size_t)bh * DH_ * T_;

    // ---- prologue: Q tile (group 0), KV tile 0 (group 1)
    {
        const __nv_bfloat16* qh = g_qhi + (size_t)(bh * T_ + q0) * DH_;
        const __nv_bfloat16* ql = g_qlo + (size_t)(bh * T_ + q0) * DH_;
#pragma unroll
        for (int it = 0; it < 4; it++) {
            const int idx = tid + it * 256;
            const int r = idx >> 3;
            const int c = idx & 7;
            const uint32_t so = sw128((uint32_t)(r * 128 + c * 16));
            CP_ASYNC_16(sb + OQHI + so, qh + (size_t)r * DH_ + c * 8);
            CP_ASYNC_16(sb + OQLO + so, ql + (size_t)r * DH_ + c * 8);
        }
        CP_ASYNC_COMMIT();
    }
    {
        const uint32_t kvb = sb + OKV;   // stage 0
#pragma unroll
        for (int it = 0; it < 2; it++) {
            const int idx = tid + it * 256;
            const int r = idx >> 3;
            const int c = idx & 7;
            const uint32_t so = sw128((uint32_t)(r * 128 + c * 16));
            CP_ASYNC_16(kvb + so,         khg + (size_t)r * DH_ + c * 8);
            CP_ASYNC_16(kvb + 8192 + so,  klg + (size_t)r * DH_ + c * 8);
            CP_ASYNC_16(kvb + 16384 + so, vhg + (size_t)r * T_ + c * 8);
            CP_ASYNC_16(kvb + 24576 + so, vlg + (size_t)r * T_ + c * 8);
        }
        CP_ASYNC_COMMIT();
    }

    float o[8][4];
#pragma unroll
    for (int ni = 0; ni < 8; ni++)
#pragma unroll
        for (int e = 0; e < 4; e++) o[ni][e] = 0.f;
    float m0 = -1e30f, m1 = -1e30f, l0 = 0.f, l1 = 0.f;

    const int row0 = q0 + 16 * w + g;
    const int kt_max = (q0 + 127) >> 6;

    for (int kt = 0; kt <= kt_max; kt++) {
        const int k0 = kt * 64;

        // prefetch next KV tile into other stage
        if (kt + 1 <= kt_max) {
            const int nk0 = (kt + 1) * 64;
            const uint32_t kvb = sb + OKV + ((kt + 1) & 1) * KVSTAGE;
#pragma unroll
            for (int it = 0; it < 2; it++) {
                const int idx = tid + it * 256;
                const int r = idx >> 3;
                const int c = idx & 7;
                const uint32_t so = sw128((uint32_t)(r * 128 + c * 16));
                CP_ASYNC_16(kvb + so,         khg + (size_t)(nk0 + r) * DH_ + c * 8);
                CP_ASYNC_16(kvb + 8192 + so,  klg + (size_t)(nk0 + r) * DH_ + c * 8);
                CP_ASYNC_16(kvb + 16384 + so, vhg + (size_t)r * T_ + nk0 + c * 8);
                CP_ASYNC_16(kvb + 24576 + so, vlg + (size_t)r * T_ + nk0 + c * 8);
            }
            CP_ASYNC_COMMIT();
            CP_ASYNC_WAIT_1();
        } else {
            CP_ASYNC_WAIT_0();
        }
        __syncthreads();

        const uint32_t kvb = sb + OKV + (kt & 1) * KVSTAGE;
        const uint32_t okh = kvb, okl = kvb + 8192,
                       ovh = kvb + 16384, ovl = kvb + 24576;

        const bool active = (k0 <= q0 + 16 * w + 15);
        if (active) {
            // ---- S = Q K^T (3 bf16 products)
            float s[8][4];
#pragma unroll
            for (int ni = 0; ni < 8; ni++)
#pragma unroll
                for (int e = 0; e < 4; e++) s[ni][e] = 0.f;

#pragma unroll
            for (int ks = 0; ks < 4; ks++) {
                uint32_t aqh[4], aql[4];
                {
                    const int qr = 16 * w + (lane & 15);
                    const uint32_t off = sw128(
                        (uint32_t)(qr * 128 + ks * 32 + ((lane >> 4) & 1) * 16));
                    ldsm_x4(aqh, sb + OQHI + off);
                    ldsm_x4(aql, sb + OQLO + off);
                }
                uint32_t bkh[8][2], bkl[8][2];
#pragma unroll
                for (int p = 0; p < 4; p++) {
                    const int kr = p * 16 + ((lane >> 4) & 1) * 8 + (lane & 7);
                    const uint32_t off = sw128(
                        (uint32_t)(kr * 128 + ks * 32 + ((lane >> 3) & 1) * 16));
                    uint32_t r4[4];
                    ldsm_x4(r4, okh + off);
                    bkh[2 * p][0] = r4[0]; bkh[2 * p][1] = r4[1];
                    bkh[2 * p + 1][0] = r4[2]; bkh[2 * p + 1][1] = r4[3];
                    ldsm_x4(r4, okl + off);
                    bkl[2 * p][0] = r4[0]; bkl[2 * p][1] = r4[1];
                    bkl[2 * p + 1][0] = r4[2]; bkl[2 * p + 1][1] = r4[3];
                }
#pragma unroll
                for (int ni = 0; ni < 8; ni++) {
                    mma_bf16(s[ni], aqh, bkh[ni]);
                    mma_bf16(s[ni], aqh, bkl[ni]);
                    mma_bf16(s[ni], aql, bkh[ni]);
                }
            }

            // ---- causal mask
            if (k0 + 63 > q0 + 16 * w) {
#pragma unroll
                for (int ni = 0; ni < 8; ni++) {
                    const int kb = k0 + 8 * ni + 2 * tq;
                    if (kb     > row0)     s[ni][0] = -1e30f;
                    if (kb + 1 > row0)     s[ni][1] = -1e30f;
                    if (kb     > row0 + 8) s[ni][2] = -1e30f;
                    if (kb + 1 > row0 + 8) s[ni][3] = -1e30f;
                }
            }

            // ---- online softmax
            float mx0 = -1e30f, mx1 = -1e30f;
#pragma unroll
            for (int ni = 0; ni < 8; ni++) {
                mx0 = fmaxf(mx0, fmaxf(s[ni][0], s[ni][1]));
                mx1 = fmaxf(mx1, fmaxf(s[ni][2], s[ni][3]));
            }
            mx0 = fmaxf(mx0, __shfl_xor_sync(0xffffffffu, mx0, 1));
            mx0 = fmaxf(mx0, __shfl_xor_sync(0xffffffffu, mx0, 2));
            mx1 = fmaxf(mx1, __shfl_xor_sync(0xffffffffu, mx1, 1));
            mx1 = fmaxf(mx1, __shfl_xor_sync(0xffffffffu, mx1, 2));

            const float mn0 = fmaxf(m0, mx0);
            const float mn1 = fmaxf(m1, mx1);
            const float sc0 = __expf(m0 - mn0);
            const float sc1 = __expf(m1 - mn1);
            m0 = mn0; m1 = mn1;
            l0 *= sc0; l1 *= sc1;
#pragma unroll
            for (int ni = 0; ni < 8; ni++) {
                o[ni][0] *= sc0; o[ni][1] *= sc0;
                o[ni][2] *= sc1; o[ni][3] *= sc1;
            }

            // ---- P = exp(S - m); bf16 hi/lo
            uint32_t pH01[8], pH23[8], pL01[8], pL23[8];
#pragma unroll
            for (int ni = 0; ni < 8; ni++) {
                float p0 = __expf(s[ni][0] - mn0);
                float p1 = __expf(s[ni][1] - mn0);
                float p2 = __expf(s[ni][2] - mn1);
                float p3 = __expf(s[ni][3] - mn1);
                l0 += p0 + p1;
                l1 += p2 + p3;
                __nv_bfloat162 h01 = __floats2bfloat162_rn(p0, p1);
                __nv_bfloat162 h23 = __floats2bfloat162_rn(p2, p3);
                pH01[ni] = *reinterpret_cast<uint32_t*>(&h01);
                pH23[ni] = *reinterpret_cast<uint32_t*>(&h23);
                __nv_bfloat162 l01 = __floats2bfloat162_rn(
                    p0 - __bfloat162float(h01.x), p1 - __bfloat162float(h01.y));
                __nv_bfloat162 l23 = __floats2bfloat162_rn(
                    p2 - __bfloat162float(h23.x), p3 - __bfloat162float(h23.y));
                pL01[ni] = *reinterpret_cast<uint32_t*>(&l01);
                pL23[ni] = *reinterpret_cast<uint32_t*>(&l23);
            }

            // ---- O += P V (3 products)
#pragma unroll
            for (int kg = 0; kg < 4; kg++) {
                uint32_t aph[4], apl[4];
                aph[0] = pH01[2 * kg];     aph[1] = pH23[2 * kg];
                aph[2] = pH01[2 * kg + 1]; aph[3] = pH23[2 * kg + 1];
                apl[0] = pL01[2 * kg];     apl[1] = pL23[2 * kg];
                apl[2] = pL01[2 * kg + 1]; apl[3] = pL23[2 * kg + 1];

                uint32_t bvh[8][2], bvl[8][2];
#pragma unroll
                for (int p = 0; p < 4; p++) {
                    const int dr = p * 16 + ((lane >> 4) & 1) * 8 + (lane & 7);
                    const uint32_t off = sw128(
                        (uint32_t)(dr * 128 + kg * 32 + ((lane >> 3) & 1) * 16));
                    uint32_t r4[4];
                    ldsm_x4(r4, ovh + off);
                    bvh[2 * p][0] = r4[0]; bvh[2 * p][1] = r4[1];
                    bvh[2 * p + 1][0] = r4[2]; bvh[2 * p + 1][1] = r4[3];
                    ldsm_x4(r4, ovl + off);
                    bvl[2 * p][0] = r4[0]; bvl[2 * p][1] = r4[1];
                    bvl[2 * p + 1][0] = r4[2]; bvl[2 * p + 1][1] = r4[3];
                }
#pragma unroll
                for (int ni = 0; ni < 8; ni++) {
                    mma_bf16(o[ni], aph, bvh[ni]);
                    mma_bf16(o[ni], apl, bvh[ni]);
                    mma_bf16(o[ni], aph, bvl[ni]);
                }
            }
        }
        __syncthreads();
    }

    // ---- finalize
    l0 += __shfl_xor_sync(0xffffffffu, l0, 1);
    l0 += __shfl_xor_sync(0xffffffffu, l0, 2);
    l1 += __shfl_xor_sync(0xffffffffu, l1, 1);
    l1 += __shfl_xor_sync(0xffffffffu, l1, 2);
    const float inv0 = 1.f / l0;
    const float inv1 = 1.f / l1;

    float* orow0 = out + (size_t)(b * T_ + row0) * C_ + h * DH_;
    float* orow1 = orow0 + (size_t)8 * C_;
#pragma unroll
    for (int ni = 0; ni < 8; ni++) {
        const int col = 8 * ni + 2 * tq;
        float2 v0; v0.x = o[ni][0] * inv0; v0.y = o[ni][1] * inv0;
        float2 v1; v1.x = o[ni][2] * inv1; v1.y = o[ni][3] * inv1;
        *reinterpret_cast<float2*>(orow0 + col) = v0;
        *reinterpret_cast<float2*>(orow1 + col) = v1;
    }
}

// ============================================================================
extern "C" void kernel_launch(void* const* d_in, const int* in_sizes, int n_in,
                              void* d_out, int out_size)
{
    const float* x     = (const float*)d_in[0];
    const float* w_qkv = (const float*)d_in[1];
    const float* w_out = (const float*)d_in[2];
    float*       out   = (float*)d_out;

    float *qkv, *att;
    __nv_bfloat16 *x3, *att3, *wqkv3, *wout3;
    cudaGetSymbolAddress((void**)&qkv,   g_qkv);
    cudaGetSymbolAddress((void**)&att,   g_att);
    cudaGetSymbolAddress((void**)&x3,    g_x3);
    cudaGetSymbolAddress((void**)&att3,  g_att3);
    cudaGetSymbolAddress((void**)&wqkv3, g_wqkv3);
    cudaGetSymbolAddress((void**)&wout3, g_wout3);

    cudaFuncSetAttribute(gemm_mma_kernel,
                         cudaFuncAttributeMaxDynamicSharedMemorySize, GEMM_SMEM);
    cudaFuncSetAttribute(attn_mma_kernel,
                         cudaFuncAttributeMaxDynamicSharedMemorySize, ATT_SMEM);

    // 0) split x and weights into 3-slab bf16
    {
        int n4 = (M_ * C_) / 4;
        split3_kernel<<<(n4 + 255) / 256, 256>>>(x, x3, C_, n4, 1);
        n4 = (N_QKV * C_) / 4;
        split3_kernel<<<(n4 + 255) / 256, 256>>>(w_qkv, wqkv3, C_, n4, 2);
        n4 = (C_ * C_) / 4;
        split3_kernel<<<(n4 + 255) / 256, 256>>>(w_out, wout3, C_, n4, 2);
    }
    // 1) QKV projection
    {
        dim3 grid(N_QKV / BN, M_ / BM);
        gemm_mma_kernel<<<grid, 256, GEMM_SMEM>>>(x3, wqkv3, qkv, M_, N_QKV, K3_);
    }
    // 2) attention preprocess (split + V transpose)
    {
        dim3 grid(T_ / 64, BH_);
        prep_attn_kernel<<<grid, 256>>>(qkv);
    }
    // 3) tensor-core causal attention -> g_att
    {
        dim3 grid(T_ / 128, BH_);
        attn_mma_kernel<<<grid, 256, ATT_SMEM>>>(att);
    }
    // 4) split attention output, output projection
    {
        int n4 = (M_ * C_) / 4;
        split3_kernel<<<(n4 + 255) / 256, 256>>>(att, att3, C_, n4, 1);
        dim3 grid(C_ / BN, M_ / BM);
        gemm_mma_kernel<<<grid, 256, GEMM_SMEM>>>(att3, wout3, out, M_, C_, K3_);
    }
}

// round 8
// speedup vs baseline: 3.7813x; 1.6829x over previous
#include <cuda_runtime.h>
#include <cuda_bf16.h>
#include <cstdint>

// ============================================================================
// Problem constants
// ============================================================================
constexpr int B_    = 4;
constexpr int T_    = 2048;
constexpr int C_    = 1024;
constexpr int H_    = 16;
constexpr int DH_   = 64;
constexpr int M_    = B_ * T_;        // 8192
constexpr int N_QKV = 3 * C_;         // 3072
constexpr int K3_   = 3 * C_;         // 3072
constexpr int BH_   = B_ * H_;        // 64

// ============================================================================
// Scratch (__device__ globals; no cudaMalloc allowed)
// ============================================================================
__device__ __nv_bfloat16  g_x3[(size_t)M_ * K3_];         // [8192,3072] hi|lo|hi
__device__ __nv_bfloat16  g_att3[(size_t)M_ * K3_];       // [8192,3072] hi|lo|hi
__device__ __nv_bfloat16  g_wqkv3[(size_t)N_QKV * K3_];   // hi|hi|lo
__device__ __nv_bfloat16  g_wout3[(size_t)C_ * K3_];      // hi|hi|lo
__device__ __nv_bfloat16  g_qhi[(size_t)BH_ * T_ * DH_];  // [bh][t][d], pre-scaled
__device__ __nv_bfloat16  g_qlo[(size_t)BH_ * T_ * DH_];
__device__ __nv_bfloat16  g_khi[(size_t)BH_ * T_ * DH_];
__device__ __nv_bfloat16  g_klo[(size_t)BH_ * T_ * DH_];
__device__ __nv_bfloat16  g_vthi[(size_t)BH_ * DH_ * T_]; // [bh][d][t]
__device__ __nv_bfloat16  g_vtlo[(size_t)BH_ * DH_ * T_];

// ============================================================================
// PTX helpers (base-ISA only)
// ============================================================================
__device__ __forceinline__ uint32_t smem_to_u32(const void* smem_ptr) {
    uint32_t addr;
    asm("{ .reg .u64 tmp; cvta.to.shared.u64 tmp, %1; cvt.u32.u64 %0, tmp; }"
        : "=r"(addr) : "l"(smem_ptr));
    return addr;
}
__device__ __forceinline__ void ldsm_x4(uint32_t (&r)[4], uint32_t addr) {
    asm volatile("ldmatrix.sync.aligned.m8n8.x4.shared.b16 {%0,%1,%2,%3}, [%4];"
        : "=r"(r[0]), "=r"(r[1]), "=r"(r[2]), "=r"(r[3]) : "r"(addr));
}
__device__ __forceinline__ void mma_bf16(float (&d)[4],
                                         const uint32_t (&a)[4],
                                         const uint32_t (&b)[2]) {
    asm volatile(
        "mma.sync.aligned.m16n8k16.row.col.f32.bf16.bf16.f32 "
        "{%0,%1,%2,%3}, {%4,%5,%6,%7}, {%8,%9}, {%0,%1,%2,%3};"
        : "+f"(d[0]), "+f"(d[1]), "+f"(d[2]), "+f"(d[3])
        : "r"(a[0]), "r"(a[1]), "r"(a[2]), "r"(a[3]), "r"(b[0]), "r"(b[1]));
}
#define CP_ASYNC_16(dst_u32, src_ptr) \
    asm volatile("cp.async.cg.shared.global [%0], [%1], 16;" \
        :: "r"(dst_u32), "l"(src_ptr))
#define CP_ASYNC_COMMIT() asm volatile("cp.async.commit_group;" ::: "memory")
#define CP_ASYNC_WAIT_2() asm volatile("cp.async.wait_group 2;" ::: "memory")
#define CP_ASYNC_WAIT_1() asm volatile("cp.async.wait_group 1;" ::: "memory")
#define CP_ASYNC_WAIT_0() asm volatile("cp.async.wait_group 0;" ::: "memory")

__device__ __forceinline__ uint32_t sw128(uint32_t off) {
    return off ^ ((off >> 3) & 0x70);
}

// ============================================================================
// Split fp32 -> 3-slab bf16 along K (hi|lo|hi for A, hi|hi|lo for B)
// ============================================================================
__global__ __launch_bounds__(256)
void split3_kernel(const float* __restrict__ in,
                   __nv_bfloat16* __restrict__ out3,
                   int K, int n4, int lo_slab)
{
    int i = blockIdx.x * blockDim.x + threadIdx.x;
    if (i >= n4) return;
    int e   = i * 4;
    int row = e / K;
    int col = e - row * K;
    float4 v = reinterpret_cast<const float4*>(in)[i];

    __nv_bfloat16 h0 = __float2bfloat16(v.x), h1 = __float2bfloat16(v.y);
    __nv_bfloat16 h2 = __float2bfloat16(v.z), h3 = __float2bfloat16(v.w);
    __nv_bfloat16 l0 = __float2bfloat16(v.x - __bfloat162float(h0));
    __nv_bfloat16 l1 = __float2bfloat16(v.y - __bfloat162float(h1));
    __nv_bfloat16 l2 = __float2bfloat16(v.z - __bfloat162float(h2));
    __nv_bfloat16 l3 = __float2bfloat16(v.w - __bfloat162float(h3));

    __nv_bfloat162 hA; hA.x = h0; hA.y = h1;
    __nv_bfloat162 hB; hB.x = h2; hB.y = h3;
    __nv_bfloat162 lA; lA.x = l0; lA.y = l1;
    __nv_bfloat162 lB; lB.x = l2; lB.y = l3;

    size_t base = (size_t)row * (3 * K) + col;
#pragma unroll
    for (int slab = 0; slab < 3; slab++) {
        __nv_bfloat162* p =
            reinterpret_cast<__nv_bfloat162*>(out3 + base + (size_t)slab * K);
        if (slab == lo_slab) { p[0] = lA; p[1] = lB; }
        else                 { p[0] = hA; p[1] = hB; }
    }
}

// ============================================================================
// Shared GEMM mainloop: 128x128 tile, BK=64, 3-stage cp.async, 8 warps.
// ============================================================================
constexpr int BM = 128, BN = 128, BK = 64;
constexpr int TILEB     = BM * 128;            // 16 KB
constexpr int STAGEB    = 2 * TILEB;           // 32 KB
constexpr int GEMM_SMEM = 3 * STAGEB;          // 96 KB

__device__ __forceinline__ void gemm_issue_loads(
    const __nv_bfloat16* __restrict__ A, const __nv_bfloat16* __restrict__ Bm,
    int K, int m0, int n0, int kc, uint32_t abase, uint32_t bbase, int tid)
{
#pragma unroll
    for (int s = 0; s < 4; s++) {
        const int idx = tid + s * 256;
        const int r = idx >> 3;
        const int c = idx & 7;
        const uint32_t so = sw128((uint32_t)(r * 128 + c * 16));
        const __nv_bfloat16* ga = A  + (size_t)(m0 + r) * K + kc + c * 8;
        const __nv_bfloat16* gb = Bm + (size_t)(n0 + r) * K + kc + c * 8;
        CP_ASYNC_16(abase + so, ga);
        CP_ASYNC_16(bbase + so, gb);
    }
}

__device__ __forceinline__ void gemm_mainloop(
    const __nv_bfloat16* __restrict__ A, const __nv_bfloat16* __restrict__ Bm,
    int K, int m0, int n0, uint32_t sbase, int tid, int wm, int wn, int lane,
    float (&acc)[4][4][4])
{
    const int NC = K / BK;

    gemm_issue_loads(A, Bm, K, m0, n0, 0, sbase, sbase + TILEB, tid);
    CP_ASYNC_COMMIT();
    if (NC > 1) {
        gemm_issue_loads(A, Bm, K, m0, n0, BK,
                         sbase + STAGEB, sbase + STAGEB + TILEB, tid);
    }
    CP_ASYNC_COMMIT();

    int stage = 0;
    for (int ch = 0; ch < NC; ch++) {
        if (ch + 2 < NC) {
            const int ns = (ch + 2) % 3;
            gemm_issue_loads(A, Bm, K, m0, n0, (ch + 2) * BK,
                             sbase + ns * STAGEB, sbase + ns * STAGEB + TILEB, tid);
            CP_ASYNC_COMMIT();
            CP_ASYNC_WAIT_2();
        } else if (ch + 1 < NC) {
            CP_ASYNC_WAIT_1();
        } else {
            CP_ASYNC_WAIT_0();
        }
        __syncthreads();

        const uint32_t abase = sbase + stage * STAGEB;
        const uint32_t bbase = abase + TILEB;

#pragma unroll
        for (int ks = 0; ks < 4; ks++) {
            uint32_t afr[4][4];
#pragma unroll
            for (int mi = 0; mi < 4; mi++) {
                const int row = wm + mi * 16 + (lane & 15);
                const uint32_t off =
                    sw128((uint32_t)(row * 128 + ks * 32 + ((lane >> 4) & 1) * 16));
                ldsm_x4(afr[mi], abase + off);
            }
            uint32_t bfr[4][2];
#pragma unroll
            for (int np = 0; np < 2; np++) {
                const int row = wn + np * 16 + ((lane >> 4) & 1) * 8 + (lane & 7);
                const uint32_t off =
                    sw128((uint32_t)(row * 128 + ks * 32 + ((lane >> 3) & 1) * 16));
                uint32_t r4[4];
                ldsm_x4(r4, bbase + off);
                bfr[2 * np][0]     = r4[0]; bfr[2 * np][1]     = r4[1];
                bfr[2 * np + 1][0] = r4[2]; bfr[2 * np + 1][1] = r4[3];
            }
#pragma unroll
            for (int mi = 0; mi < 4; mi++)
#pragma unroll
                for (int ni = 0; ni < 4; ni++)
                    mma_bf16(acc[mi][ni], afr[mi], bfr[ni]);
        }
        __syncthreads();
        stage = (stage + 1) % 3;
    }
}

// ============================================================================
// Plain GEMM (fp32 output) — used for the output projection.
// ============================================================================
__global__ __launch_bounds__(256, 2)
void gemm_mma_kernel(const __nv_bfloat16* __restrict__ A,
                     const __nv_bfloat16* __restrict__ Bm,
                     float* __restrict__ Cm,
                     int M, int N, int K)
{
    extern __shared__ char sm[];
    const int tid  = threadIdx.x;
    const int wid  = tid >> 5;
    const int lane = tid & 31;
    const int m0 = blockIdx.y * BM;
    const int n0 = blockIdx.x * BN;
    const int wm = (wid & 1) * 64;
    const int wn = (wid >> 1) * 32;

    float acc[4][4][4];
#pragma unroll
    for (int mi = 0; mi < 4; mi++)
#pragma unroll
        for (int ni = 0; ni < 4; ni++)
#pragma unroll
            for (int e = 0; e < 4; e++) acc[mi][ni][e] = 0.f;

    gemm_mainloop(A, Bm, K, m0, n0, smem_to_u32(sm), tid, wm, wn, lane, acc);

    const int g  = lane >> 2;
    const int tg = lane & 3;
#pragma unroll
    for (int mi = 0; mi < 4; mi++) {
#pragma unroll
        for (int ni = 0; ni < 4; ni++) {
            const int row = m0 + wm + mi * 16 + g;
            const int col = n0 + wn + ni * 8 + tg * 2;
            float2 p0; p0.x = acc[mi][ni][0]; p0.y = acc[mi][ni][1];
            float2 p1; p1.x = acc[mi][ni][2]; p1.y = acc[mi][ni][3];
            *reinterpret_cast<float2*>(&Cm[(size_t)row * N + col])       = p0;
            *reinterpret_cast<float2*>(&Cm[(size_t)(row + 8) * N + col]) = p1;
        }
    }
}

// ============================================================================
// QKV GEMM with fused attention-prep epilogue.
// Tile staged in smem fp32 with EVEN stride 130 (float2-aligned for all rows).
// ============================================================================
constexpr int SFS = 130;   // fp32 staging stride (even => 8B alignment holds)

__global__ __launch_bounds__(256, 2)
void gemm_qkv_fused_kernel(const __nv_bfloat16* __restrict__ A,
                           const __nv_bfloat16* __restrict__ Bm)
{
    extern __shared__ char sm[];
    const int tid  = threadIdx.x;
    const int wid  = tid >> 5;
    const int lane = tid & 31;
    const int m0 = blockIdx.y * BM;
    const int n0 = blockIdx.x * BN;
    const int wm = (wid & 1) * 64;
    const int wn = (wid >> 1) * 32;

    float acc[4][4][4];
#pragma unroll
    for (int mi = 0; mi < 4; mi++)
#pragma unroll
        for (int ni = 0; ni < 4; ni++)
#pragma unroll
            for (int e = 0; e < 4; e++) acc[mi][ni][e] = 0.f;

    gemm_mainloop(A, Bm, K3_, m0, n0, smem_to_u32(sm), tid, wm, wn, lane, acc);

    // ---- stage tile to smem fp32 [128][SFS]
    float* sf = reinterpret_cast<float*>(sm);
    const int g  = lane >> 2;
    const int tg = lane & 3;
#pragma unroll
    for (int mi = 0; mi < 4; mi++) {
#pragma unroll
        for (int ni = 0; ni < 4; ni++) {
            const int row = wm + mi * 16 + g;
            const int col = wn + ni * 8 + tg * 2;
            sf[row * SFS + col]           = acc[mi][ni][0];
            sf[row * SFS + col + 1]       = acc[mi][ni][1];
            sf[(row + 8) * SFS + col]     = acc[mi][ni][2];
            sf[(row + 8) * SFS + col + 1] = acc[mi][ni][3];
        }
    }
    __syncthreads();

    const int region = n0 >> 10;          // 0=Q, 1=K, 2=V
    const int h2     = (n0 & 1023) >> 6;  // first of 2 heads in this tile
    const int b      = m0 >> 11;
    const int t0     = m0 & 2047;
    const int w      = wid;

    if (region < 2) {
        __nv_bfloat16* dhi = (region == 0) ? g_qhi : g_khi;
        __nv_bfloat16* dlo = (region == 0) ? g_qlo : g_klo;
        const float scl = (region == 0) ? 0.125f : 1.0f;
#pragma unroll
        for (int i = 0; i < 16; i++) {
            const int t = w * 16 + i;
#pragma unroll
            for (int hh = 0; hh < 2; hh++) {
                float2 v = *reinterpret_cast<float2*>(&sf[t * SFS + hh * 64 + lane * 2]);
                v.x *= scl; v.y *= scl;
                __nv_bfloat162 hi2 = __floats2bfloat162_rn(v.x, v.y);
                __nv_bfloat162 lo2 = __floats2bfloat162_rn(
                    v.x - __bfloat162float(hi2.x), v.y - __bfloat162float(hi2.y));
                const int bh = b * 16 + h2 + hh;
                const size_t off = ((size_t)bh * T_ + t0 + t) * DH_ + lane * 2;
                *reinterpret_cast<__nv_bfloat162*>(dhi + off) = hi2;
                *reinterpret_cast<__nv_bfloat162*>(dlo + off) = lo2;
            }
        }
    } else {
        // V: write transposed [bh][d][t]
#pragma unroll
        for (int i = 0; i < 16; i++) {
            const int fd = w * 16 + i;          // 0..127 within tile
            const int hh = fd >> 6;
            const int d  = fd & 63;
            const int bh = b * 16 + h2 + hh;
            const size_t rowbase = ((size_t)bh * DH_ + d) * T_ + t0;
#pragma unroll
            for (int j = 0; j < 4; j++) {
                const int t = lane + 32 * j;
                float v = sf[t * SFS + fd];
                __nv_bfloat16 hv = __float2bfloat16(v);
                __nv_bfloat16 lv = __float2bfloat16(v - __bfloat162float(hv));
                g_vthi[rowbase + t] = hv;
                g_vtlo[rowbase + t] = lv;
            }
        }
    }
}

// ============================================================================
// Tensor-core flash attention (causal), double-buffered K/V.
// Epilogue writes 3-slab att3 (hi|lo|hi) directly.
// ============================================================================
constexpr int ATT_SMEM = 96 * 1024;
constexpr uint32_t OQHI = 0, OQLO = 16384, OKV = 32768, KVSTAGE = 32768;

__global__ __launch_bounds__(256, 2)
void attn_mma_kernel()
{
    extern __shared__ char sm[];
    const uint32_t sb = smem_to_u32(sm);

    const int tid  = threadIdx.x;
    const int w    = tid >> 5;
    const int lane = tid & 31;
    const int g    = lane >> 2;
    const int tq   = lane & 3;

    const int bh = blockIdx.y;
    const int b  = bh >> 4;
    const int h  = bh & 15;
    const int qt = gridDim.x - 1 - blockIdx.x;
    const int q0 = qt * 128;

    const __nv_bfloat16* khg = g_khi + (size_t)bh * T_ * DH_;
    const __nv_bfloat16* klg = g_klo + (size_t)bh * T_ * DH_;
    const __nv_bfloat16* vhg = g_vthi + (size_t)bh * DH_ * T_;
    const __nv_bfloat16* vlg = g_vtlo + (size_t)bh * DH_ * T_;

    {
        const __nv_bfloat16* qh = g_qhi + (size_t)(bh * T_ + q0) * DH_;
        const __nv_bfloat16* ql = g_qlo + (size_t)(bh * T_ + q0) * DH_;
#pragma unroll
        for (int it = 0; it < 4; it++) {
            const int idx = tid + it * 256;
            const int r = idx >> 3;
            const int c = idx & 7;
            const uint32_t so = sw128((uint32_t)(r * 128 + c * 16));
            CP_ASYNC_16(sb + OQHI + so, qh + (size_t)r * DH_ + c * 8);
            CP_ASYNC_16(sb + OQLO + so, ql + (size_t)r * DH_ + c * 8);
        }
        CP_ASYNC_COMMIT();
    }
    {
        const uint32_t kvb = sb + OKV;
#pragma unroll
        for (int it = 0; it < 2; it++) {
            const int idx = tid + it * 256;
            const int r = idx >> 3;
            const int c = idx & 7;
            const uint32_t so = sw128((uint32_t)(r * 128 + c * 16));
            CP_ASYNC_16(kvb + so,         khg + (size_t)r * DH_ + c * 8);
            CP_ASYNC_16(kvb + 8192 + so,  klg + (size_t)r * DH_ + c * 8);
            CP_ASYNC_16(kvb + 16384 + so, vhg + (size_t)r * T_ + c * 8);
            CP_ASYNC_16(kvb + 24576 + so, vlg + (size_t)r * T_ + c * 8);
        }
        CP_ASYNC_COMMIT();
    }

    float o[8][4];
#pragma unroll
    for (int ni = 0; ni < 8; ni++)
#pragma unroll
        for (int e = 0; e < 4; e++) o[ni][e] = 0.f;
    float m0 = -1e30f, m1 = -1e30f, l0 = 0.f, l1 = 0.f;

    const int row0 = q0 + 16 * w + g;
    const int kt_max = (q0 + 127) >> 6;

    for (int kt = 0; kt <= kt_max; kt++) {
        const int k0 = kt * 64;

        if (kt + 1 <= kt_max) {
            const int nk0 = (kt + 1) * 64;
            const uint32_t kvb = sb + OKV + ((kt + 1) & 1) * KVSTAGE;
#pragma unroll
            for (int it = 0; it < 2; it++) {
                const int idx = tid + it * 256;
                const int r = idx >> 3;
                const int c = idx & 7;
                const uint32_t so = sw128((uint32_t)(r * 128 + c * 16));
                CP_ASYNC_16(kvb + so,         khg + (size_t)(nk0 + r) * DH_ + c * 8);
                CP_ASYNC_16(kvb + 8192 + so,  klg + (size_t)(nk0 + r) * DH_ + c * 8);
                CP_ASYNC_16(kvb + 16384 + so, vhg + (size_t)r * T_ + nk0 + c * 8);
                CP_ASYNC_16(kvb + 24576 + so, vlg + (size_t)r * T_ + nk0 + c * 8);
            }
            CP_ASYNC_COMMIT();
            CP_ASYNC_WAIT_1();
        } else {
            CP_ASYNC_WAIT_0();
        }
        __syncthreads();

        const uint32_t kvb = sb + OKV + (kt & 1) * KVSTAGE;
        const uint32_t okh = kvb, okl = kvb + 8192,
                       ovh = kvb + 16384, ovl = kvb + 24576;

        const bool active = (k0 <= q0 + 16 * w + 15);
        if (active) {
            float s[8][4];
#pragma unroll
            for (int ni = 0; ni < 8; ni++)
#pragma unroll
                for (int e = 0; e < 4; e++) s[ni][e] = 0.f;

#pragma unroll
            for (int ks = 0; ks < 4; ks++) {
                uint32_t aqh[4], aql[4];
                {
                    const int qr = 16 * w + (lane & 15);
                    const uint32_t off = sw128(
                        (uint32_t)(qr * 128 + ks * 32 + ((lane >> 4) & 1) * 16));
                    ldsm_x4(aqh, sb + OQHI + off);
                    ldsm_x4(aql, sb + OQLO + off);
                }
                uint32_t bkh[8][2], bkl[8][2];
#pragma unroll
                for (int p = 0; p < 4; p++) {
                    const int kr = p * 16 + ((lane >> 4) & 1) * 8 + (lane & 7);
                    const uint32_t off = sw128(
                        (uint32_t)(kr * 128 + ks * 32 + ((lane >> 3) & 1) * 16));
                    uint32_t r4[4];
                    ldsm_x4(r4, okh + off);
                    bkh[2 * p][0] = r4[0]; bkh[2 * p][1] = r4[1];
                    bkh[2 * p + 1][0] = r4[2]; bkh[2 * p + 1][1] = r4[3];
                    ldsm_x4(r4, okl + off);
                    bkl[2 * p][0] = r4[0]; bkl[2 * p][1] = r4[1];
                    bkl[2 * p + 1][0] = r4[2]; bkl[2 * p + 1][1] = r4[3];
                }
#pragma unroll
                for (int ni = 0; ni < 8; ni++) {
                    mma_bf16(s[ni], aqh, bkh[ni]);
                    mma_bf16(s[ni], aqh, bkl[ni]);
                    mma_bf16(s[ni], aql, bkh[ni]);
                }
            }

            if (k0 + 63 > q0 + 16 * w) {
#pragma unroll
                for (int ni = 0; ni < 8; ni++) {
                    const int kb = k0 + 8 * ni + 2 * tq;
                    if (kb     > row0)     s[ni][0] = -1e30f;
                    if (kb + 1 > row0)     s[ni][1] = -1e30f;
                    if (kb     > row0 + 8) s[ni][2] = -1e30f;
                    if (kb + 1 > row0 + 8) s[ni][3] = -1e30f;
                }
            }

            float mx0 = -1e30f, mx1 = -1e30f;
#pragma unroll
            for (int ni = 0; ni < 8; ni++) {
                mx0 = fmaxf(mx0, fmaxf(s[ni][0], s[ni][1]));
                mx1 = fmaxf(mx1, fmaxf(s[ni][2], s[ni][3]));
            }
            mx0 = fmaxf(mx0, __shfl_xor_sync(0xffffffffu, mx0, 1));
            mx0 = fmaxf(mx0, __shfl_xor_sync(0xffffffffu, mx0, 2));
            mx1 = fmaxf(mx1, __shfl_xor_sync(0xffffffffu, mx1, 1));
            mx1 = fmaxf(mx1, __shfl_xor_sync(0xffffffffu, mx1, 2));

            const float mn0 = fmaxf(m0, mx0);
            const float mn1 = fmaxf(m1, mx1);
            const float sc0 = __expf(m0 - mn0);
            const float sc1 = __expf(m1 - mn1);
            m0 = mn0; m1 = mn1;
            l0 *= sc0; l1 *= sc1;
#pragma unroll
            for (int ni = 0; ni < 8; ni++) {
                o[ni][0] *= sc0; o[ni][1] *= sc0;
                o[ni][2] *= sc1; o[ni][3] *= sc1;
            }

            uint32_t pH01[8], pH23[8], pL01[8], pL23[8];
#pragma unroll
            for (int ni = 0; ni < 8; ni++) {
                float p0 = __expf(s[ni][0] - mn0);
                float p1 = __expf(s[ni][1] - mn0);
                float p2 = __expf(s[ni][2] - mn1);
                float p3 = __expf(s[ni][3] - mn1);
                l0 += p0 + p1;
                l1 += p2 + p3;
                __nv_bfloat162 h01 = __floats2bfloat162_rn(p0, p1);
                __nv_bfloat162 h23 = __floats2bfloat162_rn(p2, p3);
                pH01[ni] = *reinterpret_cast<uint32_t*>(&h01);
                pH23[ni] = *reinterpret_cast<uint32_t*>(&h23);
                __nv_bfloat162 l01 = __floats2bfloat162_rn(
                    p0 - __bfloat162float(h01.x), p1 - __bfloat162float(h01.y));
                __nv_bfloat162 l23 = __floats2bfloat162_rn(
                    p2 - __bfloat162float(h23.x), p3 - __bfloat162float(h23.y));
                pL01[ni] = *reinterpret_cast<uint32_t*>(&l01);
                pL23[ni] = *reinterpret_cast<uint32_t*>(&l23);
            }

#pragma unroll
            for (int kg = 0; kg < 4; kg++) {
                uint32_t aph[4], apl[4];
                aph[0] = pH01[2 * kg];     aph[1] = pH23[2 * kg];
                aph[2] = pH01[2 * kg + 1]; aph[3] = pH23[2 * kg + 1];
                apl[0] = pL01[2 * kg];     apl[1] = pL23[2 * kg];
                apl[2] = pL01[2 * kg + 1]; apl[3] = pL23[2 * kg + 1];

                uint32_t bvh[8][2], bvl[8][2];
#pragma unroll
                for (int p = 0; p < 4; p++) {
                    const int dr = p * 16 + ((lane >> 4) & 1) * 8 + (lane & 7);
                    const uint32_t off = sw128(
                        (uint32_t)(dr * 128 + kg * 32 + ((lane >> 3) & 1) * 16));
                    uint32_t r4[4];
                    ldsm_x4(r4, ovh + off);
                    bvh[2 * p][0] = r4[0]; bvh[2 * p][1] = r4[1];
                    bvh[2 * p + 1][0] = r4[2]; bvh[2 * p + 1][1] = r4[3];
                    ldsm_x4(r4, ovl + off);
                    bvl[2 * p][0] = r4[0]; bvl[2 * p][1] = r4[1];
                    bvl[2 * p + 1][0] = r4[2]; bvl[2 * p + 1][1] = r4[3];
                }
#pragma unroll
                for (int ni = 0; ni < 8; ni++) {
                    mma_bf16(o[ni], aph, bvh[ni]);
                    mma_bf16(o[ni], apl, bvh[ni]);
                    mma_bf16(o[ni], aph, bvl[ni]);
                }
            }
        }
        __syncthreads();
    }

    // ---- finalize: normalize, write 3-slab att3 (hi|lo|hi) directly
    l0 += __shfl_xor_sync(0xffffffffu, l0, 1);
    l0 += __shfl_xor_sync(0xffffffffu, l0, 2);
    l1 += __shfl_xor_sync(0xffffffffu, l1, 1);
    l1 += __shfl_xor_sync(0xffffffffu, l1, 2);
    const float inv0 = 1.f / l0;
    const float inv1 = 1.f / l1;

    const size_t rbase0 = (size_t)(b * T_ + row0) * K3_ + h * DH_;
    const size_t rbase1 = rbase0 + (size_t)8 * K3_;
#pragma unroll
    for (int ni = 0; ni < 8; ni++) {
        const int col = 8 * ni + 2 * tq;
        float p0 = o[ni][0] * inv0, p1 = o[ni][1] * inv0;
        float p2 = o[ni][2] * inv1, p3 = o[ni][3] * inv1;

        __nv_bfloat162 h01 = __floats2bfloat162_rn(p0, p1);
        __nv_bfloat162 l01 = __floats2bfloat162_rn(
            p0 - __bfloat162float(h01.x), p1 - __bfloat162float(h01.y));
        *reinterpret_cast<__nv_bfloat162*>(g_att3 + rbase0 + col)            = h01;
        *reinterpret_cast<__nv_bfloat162*>(g_att3 + rbase0 + C_ + col)       = l01;
        *reinterpret_cast<__nv_bfloat162*>(g_att3 + rbase0 + 2 * C_ + col)   = h01;

        __nv_bfloat162 h23 = __floats2bfloat162_rn(p2, p3);
        __nv_bfloat162 l23 = __floats2bfloat162_rn(
            p2 - __bfloat162float(h23.x), p3 - __bfloat162float(h23.y));
        *reinterpret_cast<__nv_bfloat162*>(g_att3 + rbase1 + col)            = h23;
        *reinterpret_cast<__nv_bfloat162*>(g_att3 + rbase1 + C_ + col)       = l23;
        *reinterpret_cast<__nv_bfloat162*>(g_att3 + rbase1 + 2 * C_ + col)   = h23;
    }
}

// ============================================================================
extern "C" void kernel_launch(void* const* d_in, const int* in_sizes, int n_in,
                              void* d_out, int out_size)
{
    const float* x     = (const float*)d_in[0];
    const float* w_qkv = (const float*)d_in[1];
    const float* w_out = (const float*)d_in[2];
    float*       out   = (float*)d_out;

    __nv_bfloat16 *x3, *att3, *wqkv3, *wout3;
    cudaGetSymbolAddress((void**)&x3,    g_x3);
    cudaGetSymbolAddress((void**)&att3,  g_att3);
    cudaGetSymbolAddress((void**)&wqkv3, g_wqkv3);
    cudaGetSymbolAddress((void**)&wout3, g_wout3);

    cudaFuncSetAttribute(gemm_mma_kernel,
                         cudaFuncAttributeMaxDynamicSharedMemorySize, GEMM_SMEM);
    cudaFuncSetAttribute(gemm_qkv_fused_kernel,
                         cudaFuncAttributeMaxDynamicSharedMemorySize, GEMM_SMEM);
    cudaFuncSetAttribute(attn_mma_kernel,
                         cudaFuncAttributeMaxDynamicSharedMemorySize, ATT_SMEM);

    // 0) split x and weights into 3-slab bf16
    {
        int n4 = (M_ * C_) / 4;
        split3_kernel<<<(n4 + 255) / 256, 256>>>(x, x3, C_, n4, 1);
        n4 = (N_QKV * C_) / 4;
        split3_kernel<<<(n4 + 255) / 256, 256>>>(w_qkv, wqkv3, C_, n4, 2);
        n4 = (C_ * C_) / 4;
        split3_kernel<<<(n4 + 255) / 256, 256>>>(w_out, wout3, C_, n4, 2);
    }
    // 1) QKV projection + fused attention prep (no fp32 qkv roundtrip)
    {
        dim3 grid(N_QKV / BN, M_ / BM);
        gemm_qkv_fused_kernel<<<grid, 256, GEMM_SMEM>>>(x3, wqkv3);
    }
    // 2) tensor-core causal attention -> att3 (3-slab, fused split)
    {
        dim3 grid(T_ / 128, BH_);
        attn_mma_kernel<<<grid, 256, ATT_SMEM>>>();
    }
    // 3) output projection
    {
        dim3 grid(C_ / BN, M_ / BM);
        gemm_mma_kernel<<<grid, 256, GEMM_SMEM>>>(att3, wout3, out, M_, C_, K3_);
    }
}